// round 1
// baseline (speedup 1.0000x reference)
#include <cuda_runtime.h>
#include <cstdint>

// Problem dims (fixed for this dataset)
#define BB    16
#define CC    256
#define INTER 128
#define NN    2048            // H*W = 64*32
#define PROJ_ROWS 384         // theta(128) + phi(128) + g(128)

// ---------------- scratch (no allocation allowed) ----------------
__device__ float d_proj [ (size_t)BB * PROJ_ROWS * NN ];   // [b][384][2048]  ~48MB
__device__ float d_Mpart[ (size_t)BB * 4 * INTER * INTER ];// 4 k-splits       4MB
__device__ float d_M    [ (size_t)BB * INTER * INTER ];    // [b][k][d]
__device__ float d_Q    [ (size_t)BB * CC * INTER ];       // [b][c][k]
__device__ float d_z    [ (size_t)BB * CC * NN ];          // [b][c][n]       32MB
__device__ float d_stats[ 2 * CC ];                        // scale, shift per channel

// ---------------- 64x64x16 fp32 GEMM core (A row-major MxK, B row-major KxN) ----------------
// 256 threads, each computes a 4x4 micro-tile. Caller passes A offset to its m0 row,
// B offset to its n0 column.
__device__ __forceinline__ void gemm64_core(
    const float* __restrict__ A, int lda,
    const float* __restrict__ B, int ldb,
    int K,
    float (&As)[16][68], float (&Bs)[16][64],
    float (&acc)[4][4])
{
    const int tid = threadIdx.x;
    const int txq = (tid & 15) * 4;   // n offset
    const int tyq = (tid >> 4) * 4;   // m offset
    for (int k0 = 0; k0 < K; k0 += 16) {
        #pragma unroll
        for (int i = 0; i < 4; i++) {
            int idx = tid + i * 256;          // 64x16 A tile
            int m = idx >> 4, k = idx & 15;
            As[k][m] = A[(size_t)m * lda + k0 + k];
        }
        #pragma unroll
        for (int i = 0; i < 4; i++) {
            int idx = tid + i * 256;          // 16x64 B tile
            int k = idx >> 6, n = idx & 63;
            Bs[k][n] = B[(size_t)(k0 + k) * ldb + n];
        }
        __syncthreads();
        #pragma unroll
        for (int k = 0; k < 16; k++) {
            float4 av = *(const float4*)&As[k][tyq];
            float4 bv = *(const float4*)&Bs[k][txq];
            float a[4] = {av.x, av.y, av.z, av.w};
            float b[4] = {bv.x, bv.y, bv.z, bv.w};
            #pragma unroll
            for (int i = 0; i < 4; i++)
                #pragma unroll
                for (int j = 0; j < 4; j++)
                    acc[i][j] += a[i] * b[j];
        }
        __syncthreads();
    }
}

// ---------------- Kernel 1: projections theta/phi/g ----------------
// proj[b][0:128]=theta, [128:256]=phi, [256:384]=g ;  proj = W[128,256] @ x_b[256,2048] + bias
__global__ __launch_bounds__(256) void proj_kernel(
    const float* __restrict__ x,
    const float* __restrict__ tw, const float* __restrict__ tb,
    const float* __restrict__ pw, const float* __restrict__ pb,
    const float* __restrict__ gw, const float* __restrict__ gb)
{
    __shared__ float As[16][68];
    __shared__ float Bs[16][64];
    const int b  = blockIdx.z;
    const int ty = blockIdx.y;               // 0..5 -> which 64 rows of the stacked 384
    const int n0 = blockIdx.x * 64;
    const float* W;  const float* bias;
    if (ty < 2)      { W = tw; bias = tb; }
    else if (ty < 4) { W = pw; bias = pb; }
    else             { W = gw; bias = gb; }
    const int m0 = (ty & 1) * 64;

    float acc[4][4] = {};
    gemm64_core(W + (size_t)m0 * CC, CC,
                x + (size_t)b * CC * NN + n0, NN,
                CC, As, Bs, acc);

    float* C = d_proj + ((size_t)b * PROJ_ROWS + ty * 64) * NN + n0;
    const int txq = (threadIdx.x & 15) * 4;
    const int tyq = (threadIdx.x >> 4) * 4;
    #pragma unroll
    for (int i = 0; i < 4; i++) {
        float bv = bias[m0 + tyq + i];
        float4 v = make_float4(acc[i][0] + bv, acc[i][1] + bv, acc[i][2] + bv, acc[i][3] + bv);
        *(float4*)&C[(size_t)(tyq + i) * NN + txq] = v;
    }
}

// ---------------- Kernel 2: M partials  M[k][d] = sum_n phi[k,n]*g[d,n]  (split-K over n) ----------------
__global__ __launch_bounds__(256) void m_partial_kernel()
{
    const int b = blockIdx.z >> 2;
    const int s = blockIdx.z & 3;            // n-split: 4 x 512
    const int k0r = blockIdx.y * 32;         // phi row tile
    const int d0  = blockIdx.x * 32;         // g row tile
    const float* phi = d_proj + ((size_t)b * PROJ_ROWS + 128 + k0r) * NN;
    const float* g   = d_proj + ((size_t)b * PROJ_ROWS + 256 + d0 ) * NN;
    const int nbase = s * 512;

    __shared__ float As[32][65];
    __shared__ float Bs[32][65];
    const int tid = threadIdx.x;
    const int ry = (tid >> 4) * 2;
    const int rx = (tid & 15) * 2;
    float acc[2][2] = {};

    for (int n0 = nbase; n0 < nbase + 512; n0 += 64) {
        #pragma unroll
        for (int i = 0; i < 8; i++) {
            int e = tid + i * 256;
            int r = e >> 6, c = e & 63;
            As[r][c] = phi[(size_t)r * NN + n0 + c];
            Bs[r][c] = g  [(size_t)r * NN + n0 + c];
        }
        __syncthreads();
        #pragma unroll 16
        for (int c = 0; c < 64; c++) {
            float a0 = As[ry][c],  a1 = As[ry + 1][c];
            float b0 = Bs[rx][c],  b1 = Bs[rx + 1][c];
            acc[0][0] += a0 * b0;  acc[0][1] += a0 * b1;
            acc[1][0] += a1 * b0;  acc[1][1] += a1 * b1;
        }
        __syncthreads();
    }
    float* out = d_Mpart + (((size_t)b * 4 + s) * INTER + k0r) * INTER + d0;
    out[(size_t)ry * INTER + rx]           = acc[0][0];
    out[(size_t)ry * INTER + rx + 1]       = acc[0][1];
    out[(size_t)(ry + 1) * INTER + rx]     = acc[1][0];
    out[(size_t)(ry + 1) * INTER + rx + 1] = acc[1][1];
}

// ---------------- Kernel 3: reduce M partials, apply 1/N ----------------
__global__ __launch_bounds__(256) void m_reduce_kernel()
{
    const int i = blockIdx.x * 256 + threadIdx.x;        // over 16*128*128 = 262144
    const int b = i >> 14;
    const int r = i & 16383;
    const float* p = d_Mpart + (size_t)b * 4 * 16384 + r;
    d_M[i] = (p[0] + p[16384] + p[32768] + p[49152]) * (1.0f / (float)NN);
}

// ---------------- Kernel 4: Q[c][k] = sum_d W_w[c,d] * M[k,d] ----------------
__global__ __launch_bounds__(256) void q_kernel(const float* __restrict__ W_w)
{
    const int b  = blockIdx.z;
    const int c0 = blockIdx.y * 32;          // W_w row tile (c)
    const int k0 = blockIdx.x * 32;          // M row tile (k)
    const float* A  = W_w + (size_t)c0 * INTER;
    const float* Bm = d_M + (size_t)b * INTER * INTER + (size_t)k0 * INTER;

    __shared__ float As[32][65];
    __shared__ float Bs[32][65];
    const int tid = threadIdx.x;
    const int ry = (tid >> 4) * 2;
    const int rx = (tid & 15) * 2;
    float acc[2][2] = {};

    for (int d0 = 0; d0 < INTER; d0 += 64) {
        #pragma unroll
        for (int i = 0; i < 8; i++) {
            int e = tid + i * 256;
            int r = e >> 6, c = e & 63;
            As[r][c] = A [(size_t)r * INTER + d0 + c];
            Bs[r][c] = Bm[(size_t)r * INTER + d0 + c];
        }
        __syncthreads();
        #pragma unroll 16
        for (int c = 0; c < 64; c++) {
            float a0 = As[ry][c],  a1 = As[ry + 1][c];
            float b0 = Bs[rx][c],  b1 = Bs[rx + 1][c];
            acc[0][0] += a0 * b0;  acc[0][1] += a0 * b1;
            acc[1][0] += a1 * b0;  acc[1][1] += a1 * b1;
        }
        __syncthreads();
    }
    float* out = d_Q + ((size_t)b * CC + c0) * INTER + k0;
    out[(size_t)ry * INTER + rx]           = acc[0][0];
    out[(size_t)ry * INTER + rx + 1]       = acc[0][1];
    out[(size_t)(ry + 1) * INTER + rx]     = acc[1][0];
    out[(size_t)(ry + 1) * INTER + rx + 1] = acc[1][1];
}

// ---------------- Kernel 5: z = Q[b] @ theta[b] + W_b ----------------
__global__ __launch_bounds__(256) void z_kernel(const float* __restrict__ W_b)
{
    __shared__ float As[16][68];
    __shared__ float Bs[16][64];
    const int b  = blockIdx.z;
    const int m0 = blockIdx.y * 64;          // c tile
    const int n0 = blockIdx.x * 64;

    float acc[4][4] = {};
    gemm64_core(d_Q + (size_t)b * CC * INTER + (size_t)m0 * INTER, INTER,
                d_proj + (size_t)b * PROJ_ROWS * NN + n0, NN,   // theta at row 0
                INTER, As, Bs, acc);

    float* C = d_z + ((size_t)b * CC + m0) * NN + n0;
    const int txq = (threadIdx.x & 15) * 4;
    const int tyq = (threadIdx.x >> 4) * 4;
    #pragma unroll
    for (int i = 0; i < 4; i++) {
        float bv = W_b[m0 + tyq + i];
        float4 v = make_float4(acc[i][0] + bv, acc[i][1] + bv, acc[i][2] + bv, acc[i][3] + bv);
        *(float4*)&C[(size_t)(tyq + i) * NN + txq] = v;
    }
}

// ---------------- Kernel 6: per-channel batch statistics -> (scale, shift) ----------------
__global__ __launch_bounds__(256) void bn_stats_kernel(
    const float* __restrict__ gamma, const float* __restrict__ beta)
{
    const int c = blockIdx.x;
    const int tid = threadIdx.x;
    float s = 0.f, s2 = 0.f;
    for (int b = 0; b < BB; b++) {
        const float4* p = (const float4*)(d_z + ((size_t)b * CC + c) * NN);
        for (int n = tid; n < NN / 4; n += 256) {
            float4 v = p[n];
            s  += v.x + v.y + v.z + v.w;
            s2 += v.x * v.x + v.y * v.y + v.z * v.z + v.w * v.w;
        }
    }
    __shared__ float sh0[256], sh1[256];
    sh0[tid] = s; sh1[tid] = s2;
    __syncthreads();
    for (int off = 128; off > 0; off >>= 1) {
        if (tid < off) { sh0[tid] += sh0[tid + off]; sh1[tid] += sh1[tid + off]; }
        __syncthreads();
    }
    if (tid == 0) {
        const float inv = 1.0f / (float)(BB * NN);
        float mean = sh0[0] * inv;
        float var  = sh1[0] * inv - mean * mean;
        float sc   = gamma[c] * rsqrtf(var + 1e-5f);
        d_stats[2 * c]     = sc;
        d_stats[2 * c + 1] = beta[c] - mean * sc;
    }
}

// ---------------- Kernel 7: out = z*scale + shift + x ----------------
__global__ __launch_bounds__(256) void bn_apply_kernel(
    const float* __restrict__ x, float* __restrict__ out)
{
    const size_t i = (size_t)blockIdx.x * 256 + threadIdx.x;  // float4 index, total 2097152
    const int c = (int)((i >> 9) & (CC - 1));                 // elem = i*4, channel = (elem/2048)%256
    const float sc = d_stats[2 * c];
    const float sh = d_stats[2 * c + 1];
    float4 zv = ((const float4*)d_z)[i];
    float4 xv = ((const float4*)x)[i];
    float4 o;
    o.x = zv.x * sc + sh + xv.x;
    o.y = zv.y * sc + sh + xv.y;
    o.z = zv.z * sc + sh + xv.z;
    o.w = zv.w * sc + sh + xv.w;
    ((float4*)out)[i] = o;
}

// ---------------- launch ----------------
extern "C" void kernel_launch(void* const* d_in, const int* in_sizes, int n_in,
                              void* d_out, int out_size)
{
    const float* x       = (const float*)d_in[0];
    const float* g_w     = (const float*)d_in[1];
    const float* g_b     = (const float*)d_in[2];
    const float* theta_w = (const float*)d_in[3];
    const float* theta_b = (const float*)d_in[4];
    const float* phi_w   = (const float*)d_in[5];
    const float* phi_b   = (const float*)d_in[6];
    const float* W_w     = (const float*)d_in[7];
    const float* W_b     = (const float*)d_in[8];
    const float* gamma   = (const float*)d_in[9];
    const float* beta    = (const float*)d_in[10];
    float* out = (float*)d_out;

    proj_kernel   <<<dim3(NN / 64, 6, BB), 256>>>(x, theta_w, theta_b, phi_w, phi_b, g_w, g_b);
    m_partial_kernel<<<dim3(4, 4, BB * 4), 256>>>();
    m_reduce_kernel <<<(BB * INTER * INTER) / 256, 256>>>();
    q_kernel      <<<dim3(4, 8, BB), 256>>>(W_w);
    z_kernel      <<<dim3(NN / 64, CC / 64, BB), 256>>>(W_b);
    bn_stats_kernel<<<CC, 256>>>(gamma, beta);
    bn_apply_kernel<<<(BB * CC * NN) / 4 / 256, 256>>>(x, out);
}

// round 2
// speedup vs baseline: 1.1550x; 1.1550x over previous
#include <cuda_runtime.h>
#include <cstdint>

// Problem dims (fixed)
#define BB    16
#define CC    256
#define INTER 128
#define NN    2048            // H*W
#define PR    384             // theta(128)+phi(128)+g(128)
#define MSPLIT 8

// ---------------- scratch ----------------
__device__ float d_Wt  [256 * 384];                          // packed W^T: [k][m] m: 0-127 theta,128-255 phi,256-383 g
__device__ float d_Wt2 [128 * 256];                          // W_w^T: [d][c]
__device__ float d_bias[384];
__device__ float d_proj [(size_t)BB * PR * NN];              // [b][384][2048]
__device__ float d_Mpart[(size_t)BB * MSPLIT * INTER * INTER];
__device__ float d_Qt   [(size_t)BB * INTER * CC];           // [b][k][c]
__device__ float d_z    [(size_t)BB * CC * NN];
__device__ float d_stats[2 * CC];

// ---------------- packed f32x2 helpers ----------------
__device__ __forceinline__ unsigned long long pack2(float lo, float hi) {
    unsigned long long r;
    asm("mov.b64 %0,{%1,%2};" : "=l"(r) : "f"(lo), "f"(hi));
    return r;
}
__device__ __forceinline__ void fma2(unsigned long long& d, unsigned long long a, unsigned long long b) {
    asm("fma.rn.f32x2 %0,%1,%2,%0;" : "+l"(d) : "l"(a), "l"(b));
}
__device__ __forceinline__ void unpack2(unsigned long long v, float& lo, float& hi) {
    asm("mov.b64 {%0,%1},%2;" : "=f"(lo), "=f"(hi) : "l"(v));
}

// ---------------- 128x128 tile MMA step over 16 k-values ----------------
// As[k][m], Bs[k][n]; thread (tx=tid&15, ty=tid>>4) owns rows ty*8..+7, cols tx*8..+7.
// acc[i][j] = packed pair (C[m+i][n+2j], C[m+i][n+2j+1])
__device__ __forceinline__ void mma_step(
    const float (&As)[16][128], const float (&Bs)[16][128],
    unsigned long long (&acc)[8][4], int ty8, int tx8)
{
    #pragma unroll
    for (int k = 0; k < 16; k++) {
        float4 av0 = *(const float4*)&As[k][ty8];
        float4 av1 = *(const float4*)&As[k][ty8 + 4];
        ulonglong2 bv0 = *(const ulonglong2*)&Bs[k][tx8];
        ulonglong2 bv1 = *(const ulonglong2*)&Bs[k][tx8 + 4];
        unsigned long long b[4] = { bv0.x, bv0.y, bv1.x, bv1.y };
        unsigned long long ap[8];
        ap[0] = pack2(av0.x, av0.x); ap[1] = pack2(av0.y, av0.y);
        ap[2] = pack2(av0.z, av0.z); ap[3] = pack2(av0.w, av0.w);
        ap[4] = pack2(av1.x, av1.x); ap[5] = pack2(av1.y, av1.y);
        ap[6] = pack2(av1.z, av1.z); ap[7] = pack2(av1.w, av1.w);
        #pragma unroll
        for (int i = 0; i < 8; i++)
            #pragma unroll
            for (int j = 0; j < 4; j++)
                fma2(acc[i][j], ap[i], b[j]);
    }
}

// straight [K][cols] tile loader: 16 rows x 128 cols from src (already offset to k0,row col0)
__device__ __forceinline__ void load_nn(float (&S)[16][128], const float* src, size_t ld, int tid)
{
    int k = tid >> 4, c = (tid & 15) * 8;
    const float* p = src + (size_t)k * ld + c;
    *(float4*)&S[k][c]     = *(const float4*)p;
    *(float4*)&S[k][c + 4] = *(const float4*)(p + 4);
}

// transpose loader: src row-major [128 rows][>=16 n], store S[n][row]
__device__ __forceinline__ void load_tt(float (&S)[16][128], const float* src, size_t ld, int tid)
{
    int r = tid >> 1, nq = (tid & 1) * 8;
    const float* p = src + (size_t)r * ld + nq;
    float4 v0 = *(const float4*)p;
    float4 v1 = *(const float4*)(p + 4);
    S[nq + 0][r] = v0.x; S[nq + 1][r] = v0.y; S[nq + 2][r] = v0.z; S[nq + 3][r] = v0.w;
    S[nq + 4][r] = v1.x; S[nq + 5][r] = v1.y; S[nq + 6][r] = v1.z; S[nq + 7][r] = v1.w;
}

// row-major C store with per-row bias (bias pre-offset; pass null for none)
__device__ __forceinline__ void store_c(
    float* C, size_t ldc, const float* bias,
    unsigned long long (&acc)[8][4], int ty8, int tx8)
{
    #pragma unroll
    for (int i = 0; i < 8; i++) {
        float bv = bias ? bias[ty8 + i] : 0.0f;
        float o[8];
        #pragma unroll
        for (int j = 0; j < 4; j++) unpack2(acc[i][j], o[2 * j], o[2 * j + 1]);
        float* p = C + (size_t)(ty8 + i) * ldc + tx8;
        *(float4*)p       = make_float4(o[0] + bv, o[1] + bv, o[2] + bv, o[3] + bv);
        *(float4*)(p + 4) = make_float4(o[4] + bv, o[5] + bv, o[6] + bv, o[7] + bv);
    }
}

// ---------------- Kernel 0: pack weights ----------------
__global__ __launch_bounds__(256) void pack_kernel(
    const float* __restrict__ tw, const float* __restrict__ tb,
    const float* __restrict__ pw, const float* __restrict__ pb,
    const float* __restrict__ gw, const float* __restrict__ gb,
    const float* __restrict__ Ww)
{
    int i = blockIdx.x * 256 + threadIdx.x;   // 0 .. 98303
    {   // Wt[k][m] = w_sel[m%128][k]
        int k = i / 384, m = i - k * 384;
        const float* w = (m < 128) ? tw : (m < 256) ? pw : gw;
        int mm = m & 127;
        d_Wt[i] = w[(size_t)mm * 256 + k];
    }
    if (i < 128 * 256) {  // Wt2[d][c] = Ww[c][d]
        int d = i >> 8, c = i & 255;
        d_Wt2[i] = Ww[(size_t)c * 128 + d];
    }
    if (i < 384) d_bias[i] = (i < 128) ? tb[i] : (i < 256) ? pb[i - 128] : gb[i - 256];
}

// ---------------- Kernel 1: projections (stacked) ----------------
// d_proj[b] = Wt^T(384x256) @ x_b(256x2048) + bias
__global__ __launch_bounds__(256) void proj_kernel(const float* __restrict__ x)
{
    __shared__ float As[16][128], Bs[16][128];
    unsigned long long acc[8][4] = {};
    const int b = blockIdx.z, m0 = blockIdx.y * 128, n0 = blockIdx.x * 128;
    const int tid = threadIdx.x;
    const int ty8 = (tid >> 4) * 8, tx8 = (tid & 15) * 8;
    const float* A = d_Wt + m0;                              // [256][384]
    const float* B = x + (size_t)b * CC * NN + n0;           // [256][2048]
    #pragma unroll 1
    for (int s = 0; s < 16; s++) {
        load_nn(As, A + (size_t)s * 16 * 384, 384, tid);
        load_nn(Bs, B + (size_t)s * 16 * NN, NN, tid);
        __syncthreads();
        mma_step(As, Bs, acc, ty8, tx8);
        __syncthreads();
    }
    store_c(d_proj + ((size_t)b * PR + m0) * NN + n0, NN, d_bias + m0, acc, ty8, tx8);
}

// ---------------- Kernel 2: M partials  M[k][d] += phi[k,:].g[d,:] over n-split ----------------
__global__ __launch_bounds__(256) void mpart_kernel()
{
    __shared__ float As[16][128], Bs[16][128];
    unsigned long long acc[8][4] = {};
    const int b = blockIdx.y, s = blockIdx.x;
    const int nbase = s * (NN / MSPLIT);
    const int tid = threadIdx.x;
    const int ty8 = (tid >> 4) * 8, tx8 = (tid & 15) * 8;
    const float* phi = d_proj + ((size_t)b * PR + 128) * NN + nbase;
    const float* g   = d_proj + ((size_t)b * PR + 256) * NN + nbase;
    #pragma unroll 1
    for (int st = 0; st < (NN / MSPLIT) / 16; st++) {
        load_tt(As, phi + st * 16, NN, tid);
        load_tt(Bs, g   + st * 16, NN, tid);
        __syncthreads();
        mma_step(As, Bs, acc, ty8, tx8);
        __syncthreads();
    }
    store_c(d_Mpart + (size_t)(b * MSPLIT + s) * INTER * INTER, INTER, nullptr, acc, ty8, tx8);
}

// ---------------- Kernel 3: Q^T[k][c] = sum_d W_w[c,d] * M[k,d] / N  (reduces splits inline) ----------------
__global__ __launch_bounds__(256) void q_kernel()
{
    __shared__ float As[16][128], Bs[16][128];
    unsigned long long acc[8][4] = {};
    const int b = blockIdx.y, m0 = blockIdx.x * 128;         // c tile
    const int tid = threadIdx.x;
    const int ty8 = (tid >> 4) * 8, tx8 = (tid & 15) * 8;
    const float* A = d_Wt2 + m0;                              // [128][256]
    const float* Mp = d_Mpart + (size_t)b * MSPLIT * INTER * INTER;
    const int r = tid >> 1, dq = (tid & 1) * 8;
    const float inv = 1.0f / (float)NN;
    #pragma unroll 1
    for (int st = 0; st < 8; st++) {
        load_nn(As, A + (size_t)st * 16 * 256, 256, tid);
        {   // B: transpose + split reduce: Bs[dk][k] = sum_s Mpart[s][k][d0+dk] / N
            const float* p = Mp + (size_t)r * INTER + st * 16 + dq;
            float a0 = 0, a1 = 0, a2 = 0, a3 = 0, a4 = 0, a5 = 0, a6 = 0, a7 = 0;
            #pragma unroll
            for (int sp = 0; sp < MSPLIT; sp++) {
                float4 v0 = *(const float4*)(p + (size_t)sp * INTER * INTER);
                float4 v1 = *(const float4*)(p + (size_t)sp * INTER * INTER + 4);
                a0 += v0.x; a1 += v0.y; a2 += v0.z; a3 += v0.w;
                a4 += v1.x; a5 += v1.y; a6 += v1.z; a7 += v1.w;
            }
            Bs[dq + 0][r] = a0 * inv; Bs[dq + 1][r] = a1 * inv;
            Bs[dq + 2][r] = a2 * inv; Bs[dq + 3][r] = a3 * inv;
            Bs[dq + 4][r] = a4 * inv; Bs[dq + 5][r] = a5 * inv;
            Bs[dq + 6][r] = a6 * inv; Bs[dq + 7][r] = a7 * inv;
        }
        __syncthreads();
        mma_step(As, Bs, acc, ty8, tx8);
        __syncthreads();
    }
    // transposed store: Qt[k][c]
    float o[8][8];
    #pragma unroll
    for (int i = 0; i < 8; i++)
        #pragma unroll
        for (int j = 0; j < 4; j++) unpack2(acc[i][j], o[i][2 * j], o[i][2 * j + 1]);
    float* Qt = d_Qt + (size_t)b * INTER * CC;
    #pragma unroll
    for (int c = 0; c < 8; c++) {
        float* p = Qt + (size_t)(tx8 + c) * CC + m0 + ty8;
        *(float4*)p       = make_float4(o[0][c], o[1][c], o[2][c], o[3][c]);
        *(float4*)(p + 4) = make_float4(o[4][c], o[5][c], o[6][c], o[7][c]);
    }
}

// ---------------- Kernel 4: z = Q @ theta + W_b ----------------
__global__ __launch_bounds__(256) void z_kernel(const float* __restrict__ W_b)
{
    __shared__ float As[16][128], Bs[16][128];
    unsigned long long acc[8][4] = {};
    const int b = blockIdx.z, m0 = blockIdx.y * 128, n0 = blockIdx.x * 128;
    const int tid = threadIdx.x;
    const int ty8 = (tid >> 4) * 8, tx8 = (tid & 15) * 8;
    const float* A = d_Qt + (size_t)b * INTER * CC + m0;     // [128][256]
    const float* B = d_proj + (size_t)b * PR * NN + n0;      // theta rows 0..127
    #pragma unroll 1
    for (int s = 0; s < 8; s++) {
        load_nn(As, A + (size_t)s * 16 * CC, CC, tid);
        load_nn(Bs, B + (size_t)s * 16 * NN, NN, tid);
        __syncthreads();
        mma_step(As, Bs, acc, ty8, tx8);
        __syncthreads();
    }
    store_c(d_z + ((size_t)b * CC + m0) * NN + n0, NN, W_b + m0, acc, ty8, tx8);
}

// ---------------- Kernel 5: per-channel batch stats ----------------
__global__ __launch_bounds__(256) void bn_stats_kernel(
    const float* __restrict__ gamma, const float* __restrict__ beta)
{
    const int c = blockIdx.x;
    const int tid = threadIdx.x;
    float s = 0.f, s2 = 0.f;
    for (int b = 0; b < BB; b++) {
        const float4* p = (const float4*)(d_z + ((size_t)b * CC + c) * NN);
        for (int n = tid; n < NN / 4; n += 256) {
            float4 v = p[n];
            s  += v.x + v.y + v.z + v.w;
            s2 += v.x * v.x + v.y * v.y + v.z * v.z + v.w * v.w;
        }
    }
    __shared__ float sh0[256], sh1[256];
    sh0[tid] = s; sh1[tid] = s2;
    __syncthreads();
    for (int off = 128; off > 0; off >>= 1) {
        if (tid < off) { sh0[tid] += sh0[tid + off]; sh1[tid] += sh1[tid + off]; }
        __syncthreads();
    }
    if (tid == 0) {
        const float inv = 1.0f / (float)(BB * NN);
        float mean = sh0[0] * inv;
        float var  = sh1[0] * inv - mean * mean;
        float sc   = gamma[c] * rsqrtf(var + 1e-5f);
        d_stats[2 * c]     = sc;
        d_stats[2 * c + 1] = beta[c] - mean * sc;
    }
}

// ---------------- Kernel 6: out = z*scale + shift + x ----------------
__global__ __launch_bounds__(256) void bn_apply_kernel(
    const float* __restrict__ x, float* __restrict__ out)
{
    const size_t i = (size_t)blockIdx.x * 256 + threadIdx.x;  // float4 index
    const int c = (int)((i >> 9) & (CC - 1));
    const float sc = d_stats[2 * c];
    const float sh = d_stats[2 * c + 1];
    float4 zv = ((const float4*)d_z)[i];
    float4 xv = ((const float4*)x)[i];
    float4 o;
    o.x = zv.x * sc + sh + xv.x;
    o.y = zv.y * sc + sh + xv.y;
    o.z = zv.z * sc + sh + xv.z;
    o.w = zv.w * sc + sh + xv.w;
    ((float4*)out)[i] = o;
}

// ---------------- launch ----------------
extern "C" void kernel_launch(void* const* d_in, const int* in_sizes, int n_in,
                              void* d_out, int out_size)
{
    const float* x       = (const float*)d_in[0];
    const float* g_w     = (const float*)d_in[1];
    const float* g_b     = (const float*)d_in[2];
    const float* theta_w = (const float*)d_in[3];
    const float* theta_b = (const float*)d_in[4];
    const float* phi_w   = (const float*)d_in[5];
    const float* phi_b   = (const float*)d_in[6];
    const float* W_w     = (const float*)d_in[7];
    const float* W_b     = (const float*)d_in[8];
    const float* gamma   = (const float*)d_in[9];
    const float* beta    = (const float*)d_in[10];
    float* out = (float*)d_out;

    pack_kernel   <<<384, 256>>>(theta_w, theta_b, phi_w, phi_b, g_w, g_b, W_w);
    proj_kernel   <<<dim3(NN / 128, 3, BB), 256>>>(x);
    mpart_kernel  <<<dim3(MSPLIT, BB), 256>>>();
    q_kernel      <<<dim3(2, BB), 256>>>();
    z_kernel      <<<dim3(NN / 128, 2, BB), 256>>>(W_b);
    bn_stats_kernel<<<CC, 256>>>(gamma, beta);
    bn_apply_kernel<<<(size_t)(BB * CC * NN) / 4 / 256, 256>>>(x, out);
}

// round 3
// speedup vs baseline: 2.3011x; 1.9923x over previous
#include <cuda_runtime.h>
#include <cstdint>

// Problem dims (fixed)
#define BB    16
#define CC    256
#define INTER 128
#define NN    2048
#define PR    384
#define MSPLIT 8

// ---------------- scratch ----------------
__device__ float d_Wt  [256 * 384];                 // [k][m]: m = theta|phi|g stacked
__device__ float d_Wt2 [128 * 256];                 // W_w^T: [d][c]
__device__ float d_bias[384];
__device__ float d_proj [(size_t)BB * PR * NN];     // [b][384][2048]
__device__ float d_Mpart[(size_t)BB * MSPLIT * INTER * INTER];
__device__ float d_Mred [(size_t)BB * INTER * INTER];
__device__ float d_Qt   [(size_t)BB * INTER * CC];  // [b][k][c]
__device__ float d_z    [(size_t)BB * CC * NN];
__device__ float d_stats[2 * CC];

// ---------------- tf32 helpers ----------------
__device__ __forceinline__ float tf32r(float f) {
    uint32_t r; asm("cvt.rna.tf32.f32 %0,%1;" : "=r"(r) : "f"(f));
    return __uint_as_float(r);
}
__device__ __forceinline__ void mma8(float* c, const uint32_t* a, const uint32_t* b) {
    asm volatile("mma.sync.aligned.m16n8k8.row.col.f32.tf32.tf32.f32 "
        "{%0,%1,%2,%3},{%4,%5,%6,%7},{%8,%9},{%0,%1,%2,%3};"
        : "+f"(c[0]), "+f"(c[1]), "+f"(c[2]), "+f"(c[3])
        : "r"(a[0]), "r"(a[1]), "r"(a[2]), "r"(a[3]), "r"(b[0]), "r"(b[1]));
}

// ---------------- smem tile loaders (convert to tf32 on the way in) ----------------
// direct: S[k][col] = src[k*ld + col], 16 x 128
__device__ __forceinline__ void ld_nn(float (&S)[16][136], const float* src, size_t ld, int tid)
{
    int k = tid >> 4, c = (tid & 15) * 8;
    const float* p = src + (size_t)k * ld + c;
    float4 v0 = *(const float4*)p, v1 = *(const float4*)(p + 4);
    S[k][c + 0] = tf32r(v0.x); S[k][c + 1] = tf32r(v0.y);
    S[k][c + 2] = tf32r(v0.z); S[k][c + 3] = tf32r(v0.w);
    S[k][c + 4] = tf32r(v1.x); S[k][c + 5] = tf32r(v1.y);
    S[k][c + 6] = tf32r(v1.z); S[k][c + 7] = tf32r(v1.w);
}
// transpose: S[q + j][r] = src[r*ld + q + j], 128 rows x 16 cols
__device__ __forceinline__ void ld_tt(float (&S)[16][136], const float* src, size_t ld, int tid)
{
    int r = tid >> 1, q = (tid & 1) * 8;
    const float* p = src + (size_t)r * ld + q;
    float4 v0 = *(const float4*)p, v1 = *(const float4*)(p + 4);
    S[q + 0][r] = tf32r(v0.x); S[q + 1][r] = tf32r(v0.y);
    S[q + 2][r] = tf32r(v0.z); S[q + 3][r] = tf32r(v0.w);
    S[q + 4][r] = tf32r(v1.x); S[q + 5][r] = tf32r(v1.y);
    S[q + 6][r] = tf32r(v1.z); S[q + 7][r] = tf32r(v1.w);
}

// ---------------- 128x128 mma tile over one 16-k smem tile ----------------
// 8 warps: warp_m = (wid>>2)*64, warp_n = (wid&3)*32. acc[mt][nt][4].
__device__ __forceinline__ void mma_tile(
    const float (&As)[16][136], const float (&Bs)[16][136],
    float (&acc)[4][4][4], int wm, int wn, int gid, int tig)
{
    #pragma unroll
    for (int ks = 0; ks < 2; ks++) {
        uint32_t a[4][4], b[4][2];
        const int kc = ks * 8 + tig;
        #pragma unroll
        for (int mt = 0; mt < 4; mt++) {
            int row = wm + mt * 16 + gid;
            a[mt][0] = __float_as_uint(As[kc][row]);
            a[mt][1] = __float_as_uint(As[kc][row + 8]);
            a[mt][2] = __float_as_uint(As[kc + 4][row]);
            a[mt][3] = __float_as_uint(As[kc + 4][row + 8]);
        }
        #pragma unroll
        for (int nt = 0; nt < 4; nt++) {
            int cn = wn + nt * 8 + gid;
            b[nt][0] = __float_as_uint(Bs[kc][cn]);
            b[nt][1] = __float_as_uint(Bs[kc + 4][cn]);
        }
        #pragma unroll
        for (int mt = 0; mt < 4; mt++)
            #pragma unroll
            for (int nt = 0; nt < 4; nt++)
                mma8(acc[mt][nt], a[mt], b[nt]);
    }
}

// row-major C store with optional bias
__device__ __forceinline__ void store_tile(
    float* C, size_t ldc, const float* bias,
    float (&acc)[4][4][4], int wm, int wn, int gid, int tig)
{
    #pragma unroll
    for (int mt = 0; mt < 4; mt++) {
        int r0 = wm + mt * 16 + gid, r1 = r0 + 8;
        float b0 = bias ? bias[r0] : 0.0f;
        float b1 = bias ? bias[r1] : 0.0f;
        #pragma unroll
        for (int nt = 0; nt < 4; nt++) {
            int cn = wn + nt * 8 + 2 * tig;
            *(float2*)(C + (size_t)r0 * ldc + cn) =
                make_float2(acc[mt][nt][0] + b0, acc[mt][nt][1] + b0);
            *(float2*)(C + (size_t)r1 * ldc + cn) =
                make_float2(acc[mt][nt][2] + b1, acc[mt][nt][3] + b1);
        }
    }
}

#define TILE_SETUP \
    __shared__ float As[16][136], Bs[16][136]; \
    float acc[4][4][4] = {}; \
    const int tid = threadIdx.x; \
    const int wid = tid >> 5; \
    const int wm = (wid >> 2) * 64, wn = (wid & 3) * 32; \
    const int gid = (tid & 31) >> 2, tig = tid & 3;

// ---------------- Kernel 0: pack weights ----------------
__global__ __launch_bounds__(256) void pack_kernel(
    const float* __restrict__ tw, const float* __restrict__ tb,
    const float* __restrict__ pw, const float* __restrict__ pb,
    const float* __restrict__ gw, const float* __restrict__ gb,
    const float* __restrict__ Ww)
{
    int i = blockIdx.x * 256 + threadIdx.x;   // 0 .. 98303
    {
        int k = i / 384, m = i - k * 384;
        const float* w = (m < 128) ? tw : (m < 256) ? pw : gw;
        d_Wt[i] = w[(size_t)(m & 127) * 256 + k];
    }
    if (i < 128 * 256) {
        int d = i >> 8, c = i & 255;
        d_Wt2[i] = Ww[(size_t)c * 128 + d];
    }
    if (i < 384) d_bias[i] = (i < 128) ? tb[i] : (i < 256) ? pb[i - 128] : gb[i - 256];
}

// ---------------- Kernel 1: proj[b] = Wt^T(384x256) @ x_b(256x2048) + bias ----------------
__global__ __launch_bounds__(256, 2) void proj_kernel(const float* __restrict__ x)
{
    TILE_SETUP
    const int b = blockIdx.z, m0 = blockIdx.y * 128, n0 = blockIdx.x * 128;
    const float* B = x + (size_t)b * CC * NN + n0;
    #pragma unroll 1
    for (int s = 0; s < 16; s++) {
        ld_nn(As, d_Wt + (size_t)s * 16 * 384 + m0, 384, tid);
        ld_nn(Bs, B + (size_t)s * 16 * NN, NN, tid);
        __syncthreads();
        mma_tile(As, Bs, acc, wm, wn, gid, tig);
        __syncthreads();
    }
    store_tile(d_proj + ((size_t)b * PR + m0) * NN + n0, NN, d_bias + m0, acc, wm, wn, gid, tig);
}

// ---------------- Kernel 2: M partials: Mp[s][k][d] = sum_{n in split} phi[k,n] g[d,n] ----------------
__global__ __launch_bounds__(256, 2) void mpart_kernel()
{
    TILE_SETUP
    const int b = blockIdx.y, s = blockIdx.x;
    const int nbase = s * (NN / MSPLIT);
    const float* phi = d_proj + ((size_t)b * PR + 128) * NN + nbase;
    const float* g   = d_proj + ((size_t)b * PR + 256) * NN + nbase;
    #pragma unroll 1
    for (int st = 0; st < (NN / MSPLIT) / 16; st++) {
        ld_tt(As, phi + st * 16, NN, tid);
        ld_tt(Bs, g   + st * 16, NN, tid);
        __syncthreads();
        mma_tile(As, Bs, acc, wm, wn, gid, tig);
        __syncthreads();
    }
    store_tile(d_Mpart + (size_t)(b * MSPLIT + s) * INTER * INTER, INTER, nullptr, acc, wm, wn, gid, tig);
}

// ---------------- Kernel 3: reduce split-K partials, scale by 1/N ----------------
__global__ __launch_bounds__(256) void mred_kernel()
{
    const int i = blockIdx.x * 256 + threadIdx.x;   // 262144
    const int b = i >> 14, r = i & 16383;
    const float* p = d_Mpart + (size_t)b * MSPLIT * 16384 + r;
    float s = 0.f;
    #pragma unroll
    for (int sp = 0; sp < MSPLIT; sp++) s += p[(size_t)sp * 16384];
    d_Mred[i] = s * (1.0f / (float)NN);
}

// ---------------- Kernel 4: Qt[k][c] = sum_d Mred[k][d] * Wt2[d][c] ----------------
__global__ __launch_bounds__(256, 2) void q_kernel()
{
    TILE_SETUP
    const int b = blockIdx.y, n0 = blockIdx.x * 128;   // c tile
    const float* M = d_Mred + (size_t)b * INTER * INTER;
    #pragma unroll 1
    for (int st = 0; st < 8; st++) {
        ld_tt(As, M + st * 16, INTER, tid);                         // As[d][k]
        ld_nn(Bs, d_Wt2 + (size_t)st * 16 * CC + n0, CC, tid);      // Bs[d][c]
        __syncthreads();
        mma_tile(As, Bs, acc, wm, wn, gid, tig);
        __syncthreads();
    }
    store_tile(d_Qt + (size_t)b * INTER * CC + n0, CC, nullptr, acc, wm, wn, gid, tig);
}

// ---------------- Kernel 5: z[c][n] = sum_k Qt[k][c] * theta[k][n] + W_b ----------------
__global__ __launch_bounds__(256, 2) void z_kernel(const float* __restrict__ W_b)
{
    TILE_SETUP
    const int b = blockIdx.z, m0 = blockIdx.y * 128, n0 = blockIdx.x * 128;
    const float* A = d_Qt + (size_t)b * INTER * CC + m0;    // [k][c]
    const float* B = d_proj + (size_t)b * PR * NN + n0;     // theta rows 0..127
    #pragma unroll 1
    for (int st = 0; st < 8; st++) {
        ld_nn(As, A + (size_t)st * 16 * CC, CC, tid);
        ld_nn(Bs, B + (size_t)st * 16 * NN, NN, tid);
        __syncthreads();
        mma_tile(As, Bs, acc, wm, wn, gid, tig);
        __syncthreads();
    }
    store_tile(d_z + ((size_t)b * CC + m0) * NN + n0, NN, W_b + m0, acc, wm, wn, gid, tig);
}

// ---------------- Kernel 6: per-channel batch stats ----------------
__global__ __launch_bounds__(256) void bn_stats_kernel(
    const float* __restrict__ gamma, const float* __restrict__ beta)
{
    const int c = blockIdx.x;
    const int tid = threadIdx.x;
    float s = 0.f, s2 = 0.f;
    for (int b = 0; b < BB; b++) {
        const float4* p = (const float4*)(d_z + ((size_t)b * CC + c) * NN);
        for (int n = tid; n < NN / 4; n += 256) {
            float4 v = p[n];
            s  += v.x + v.y + v.z + v.w;
            s2 += v.x * v.x + v.y * v.y + v.z * v.z + v.w * v.w;
        }
    }
    __shared__ float sh0[256], sh1[256];
    sh0[tid] = s; sh1[tid] = s2;
    __syncthreads();
    for (int off = 128; off > 0; off >>= 1) {
        if (tid < off) { sh0[tid] += sh0[tid + off]; sh1[tid] += sh1[tid + off]; }
        __syncthreads();
    }
    if (tid == 0) {
        const float inv = 1.0f / (float)(BB * NN);
        float mean = sh0[0] * inv;
        float var  = sh1[0] * inv - mean * mean;
        float sc   = gamma[c] * rsqrtf(var + 1e-5f);
        d_stats[2 * c]     = sc;
        d_stats[2 * c + 1] = beta[c] - mean * sc;
    }
}

// ---------------- Kernel 7: out = z*scale + shift + x ----------------
__global__ __launch_bounds__(256) void bn_apply_kernel(
    const float* __restrict__ x, float* __restrict__ out)
{
    const size_t i = (size_t)blockIdx.x * 256 + threadIdx.x;  // float4 index
    const int c = (int)((i >> 9) & (CC - 1));
    const float sc = d_stats[2 * c];
    const float sh = d_stats[2 * c + 1];
    float4 zv = ((const float4*)d_z)[i];
    float4 xv = ((const float4*)x)[i];
    float4 o;
    o.x = zv.x * sc + sh + xv.x;
    o.y = zv.y * sc + sh + xv.y;
    o.z = zv.z * sc + sh + xv.z;
    o.w = zv.w * sc + sh + xv.w;
    ((float4*)out)[i] = o;
}

// ---------------- launch ----------------
extern "C" void kernel_launch(void* const* d_in, const int* in_sizes, int n_in,
                              void* d_out, int out_size)
{
    const float* x       = (const float*)d_in[0];
    const float* g_w     = (const float*)d_in[1];
    const float* g_b     = (const float*)d_in[2];
    const float* theta_w = (const float*)d_in[3];
    const float* theta_b = (const float*)d_in[4];
    const float* phi_w   = (const float*)d_in[5];
    const float* phi_b   = (const float*)d_in[6];
    const float* W_w     = (const float*)d_in[7];
    const float* W_b     = (const float*)d_in[8];
    const float* gamma   = (const float*)d_in[9];
    const float* beta    = (const float*)d_in[10];
    float* out = (float*)d_out;

    pack_kernel    <<<384, 256>>>(theta_w, theta_b, phi_w, phi_b, g_w, g_b, W_w);
    proj_kernel    <<<dim3(NN / 128, 3, BB), 256>>>(x);
    mpart_kernel   <<<dim3(MSPLIT, BB), 256>>>();
    mred_kernel    <<<(BB * INTER * INTER) / 256, 256>>>();
    q_kernel       <<<dim3(2, BB), 256>>>();
    z_kernel       <<<dim3(NN / 128, 2, BB), 256>>>(W_b);
    bn_stats_kernel<<<CC, 256>>>(gamma, beta);
    bn_apply_kernel<<<(size_t)(BB * CC * NN) / 4 / 256, 256>>>(x, out);
}

// round 4
// speedup vs baseline: 2.4606x; 1.0693x over previous
#include <cuda_runtime.h>
#include <cstdint>

#define BB    16
#define CC    256
#define INTER 128
#define NN    2048
#define PR    384
#define MSPLIT 16

// ---------------- scratch ----------------
__device__ float d_Wt  [256 * 384];                 // [k][m]: theta|phi|g stacked
__device__ float d_Wt2 [128 * 256];                 // W_w^T: [d][c]
__device__ float d_bias[384];
__device__ float d_theta[(size_t)BB * INTER * NN];  // [b][128][2048]
__device__ float d_Mpart[(size_t)BB * MSPLIT * INTER * INTER];
__device__ float d_Mred [(size_t)BB * INTER * INTER];
__device__ float d_Qt   [(size_t)BB * INTER * CC];  // [b][k][c]
__device__ float d_z    [(size_t)BB * CC * NN];
__device__ float d_sums [512];                      // [0:256] sum, [256:512] sumsq
__device__ float d_stats[2 * CC];

// ---------------- tf32 helpers ----------------
__device__ __forceinline__ float tf32r(float f) {
    uint32_t r; asm("cvt.rna.tf32.f32 %0,%1;" : "=r"(r) : "f"(f));
    return __uint_as_float(r);
}
__device__ __forceinline__ void mma8(float* c, const uint32_t* a, const uint32_t* b) {
    asm volatile("mma.sync.aligned.m16n8k8.row.col.f32.tf32.tf32.f32 "
        "{%0,%1,%2,%3},{%4,%5,%6,%7},{%8,%9},{%0,%1,%2,%3};"
        : "+f"(c[0]), "+f"(c[1]), "+f"(c[2]), "+f"(c[3])
        : "r"(a[0]), "r"(a[1]), "r"(a[2]), "r"(a[3]), "r"(b[0]), "r"(b[1]));
}

// ---------------- smem tile loaders (convert to tf32 on the way in) ----------------
__device__ __forceinline__ void ld_nn(float (*S)[136], const float* src, size_t ld, int tid)
{
    int k = tid >> 4, c = (tid & 15) * 8;
    const float* p = src + (size_t)k * ld + c;
    float4 v0 = *(const float4*)p, v1 = *(const float4*)(p + 4);
    S[k][c + 0] = tf32r(v0.x); S[k][c + 1] = tf32r(v0.y);
    S[k][c + 2] = tf32r(v0.z); S[k][c + 3] = tf32r(v0.w);
    S[k][c + 4] = tf32r(v1.x); S[k][c + 5] = tf32r(v1.y);
    S[k][c + 6] = tf32r(v1.z); S[k][c + 7] = tf32r(v1.w);
}
__device__ __forceinline__ void ld_tt(float (*S)[136], const float* src, size_t ld, int tid)
{
    int r = tid >> 1, q = (tid & 1) * 8;
    const float* p = src + (size_t)r * ld + q;
    float4 v0 = *(const float4*)p, v1 = *(const float4*)(p + 4);
    S[q + 0][r] = tf32r(v0.x); S[q + 1][r] = tf32r(v0.y);
    S[q + 2][r] = tf32r(v0.z); S[q + 3][r] = tf32r(v0.w);
    S[q + 4][r] = tf32r(v1.x); S[q + 5][r] = tf32r(v1.y);
    S[q + 6][r] = tf32r(v1.z); S[q + 7][r] = tf32r(v1.w);
}

// ---------------- 128x128 mma over one 16-k slab ----------------
__device__ __forceinline__ void mma_tile(
    const float (*As)[136], const float (*Bs)[136],
    float (&acc)[4][4][4], int wm, int wn, int gid, int tig)
{
    #pragma unroll
    for (int ks = 0; ks < 2; ks++) {
        uint32_t a[4][4], b[4][2];
        const int kc = ks * 8 + tig;
        #pragma unroll
        for (int mt = 0; mt < 4; mt++) {
            int row = wm + mt * 16 + gid;
            a[mt][0] = __float_as_uint(As[kc][row]);
            a[mt][1] = __float_as_uint(As[kc][row + 8]);
            a[mt][2] = __float_as_uint(As[kc + 4][row]);
            a[mt][3] = __float_as_uint(As[kc + 4][row + 8]);
        }
        #pragma unroll
        for (int nt = 0; nt < 4; nt++) {
            int cn = wn + nt * 8 + gid;
            b[nt][0] = __float_as_uint(Bs[kc][cn]);
            b[nt][1] = __float_as_uint(Bs[kc + 4][cn]);
        }
        #pragma unroll
        for (int mt = 0; mt < 4; mt++)
            #pragma unroll
            for (int nt = 0; nt < 4; nt++)
                mma8(acc[mt][nt], a[mt], b[nt]);
    }
}

__device__ __forceinline__ void store_tile(
    float* C, size_t ldc, const float* bias,
    float (&acc)[4][4][4], int wm, int wn, int gid, int tig)
{
    #pragma unroll
    for (int mt = 0; mt < 4; mt++) {
        int r0 = wm + mt * 16 + gid, r1 = r0 + 8;
        float b0 = bias ? bias[r0] : 0.0f;
        float b1 = bias ? bias[r1] : 0.0f;
        #pragma unroll
        for (int nt = 0; nt < 4; nt++) {
            int cn = wn + nt * 8 + 2 * tig;
            *(float2*)(C + (size_t)r0 * ldc + cn) =
                make_float2(acc[mt][nt][0] + b0, acc[mt][nt][1] + b0);
            *(float2*)(C + (size_t)r1 * ldc + cn) =
                make_float2(acc[mt][nt][2] + b1, acc[mt][nt][3] + b1);
        }
    }
}

#define WARP_IDX \
    const int tid = threadIdx.x; \
    const int wid = tid >> 5; \
    const int wm = (wid >> 2) * 64, wn = (wid & 3) * 32; \
    const int gid = (tid & 31) >> 2, tig = tid & 3;

// ---------------- Kernel 0: pack weights + zero stat sums ----------------
__global__ __launch_bounds__(256) void pack_kernel(
    const float* __restrict__ tw, const float* __restrict__ tb,
    const float* __restrict__ pw, const float* __restrict__ pb,
    const float* __restrict__ gw, const float* __restrict__ gb,
    const float* __restrict__ Ww)
{
    int i = blockIdx.x * 256 + threadIdx.x;   // 0 .. 98303
    {
        int k = i / 384, m = i - k * 384;
        const float* w = (m < 128) ? tw : (m < 256) ? pw : gw;
        d_Wt[i] = w[(size_t)(m & 127) * 256 + k];
    }
    if (i < 128 * 256) {
        int d = i >> 8, c = i & 255;
        d_Wt2[i] = Ww[(size_t)c * 128 + d];
    }
    if (i < 384) d_bias[i] = (i < 128) ? tb[i] : (i < 256) ? pb[i - 128] : gb[i - 256];
    if (i < 512) d_sums[i] = 0.0f;
}

// ---------------- Kernel 1: theta only ----------------
__global__ __launch_bounds__(256, 2) void theta_kernel(const float* __restrict__ x)
{
    __shared__ float As[16][136], Bs[16][136];
    float acc[4][4][4] = {};
    WARP_IDX
    const int b = blockIdx.y, n0 = blockIdx.x * 128;
    const float* B = x + (size_t)b * CC * NN + n0;
    #pragma unroll 1
    for (int s = 0; s < 16; s++) {
        ld_nn(As, d_Wt + (size_t)s * 16 * 384, 384, tid);
        ld_nn(Bs, B + (size_t)s * 16 * NN, NN, tid);
        __syncthreads();
        mma_tile(As, Bs, acc, wm, wn, gid, tig);
        __syncthreads();
    }
    store_tile(d_theta + ((size_t)b * INTER) * NN + n0, NN, d_bias, acc, wm, wn, gid, tig);
}

// ---------------- Kernel 2: fused phi/g projection + M partial ----------------
// Per block: n-slice of 128. Stage 1: phi,g = W @ x_slice (into smem, transposed).
// Stage 2: Mpart[k][d] = sum_n phi[k,n] g[d,n].
__global__ __launch_bounds__(256, 1) void mpg_kernel(const float* __restrict__ x)
{
    extern __shared__ float sm[];
    float (*AsP)[136]  = (float(*)[136])sm;        // 16 rows
    float (*AsG)[136]  = AsP + 16;
    float (*Bsx)[136]  = AsG + 16;
    float (*phi_s)[136] = Bsx + 16;                 // 128 rows, [n][k]
    float (*g_s)[136]   = phi_s + 128;              // 128 rows, [n][d]
    WARP_IDX
    const int b = blockIdx.y, s = blockIdx.x;
    const int n0 = s * 128;
    const float* B = x + (size_t)b * CC * NN + n0;

    float accP[4][4][4] = {}, accG[4][4][4] = {};
    #pragma unroll 1
    for (int st = 0; st < 16; st++) {
        ld_nn(AsP, d_Wt + (size_t)st * 16 * 384 + 128, 384, tid);
        ld_nn(AsG, d_Wt + (size_t)st * 16 * 384 + 256, 384, tid);
        ld_nn(Bsx, B + (size_t)st * 16 * NN, NN, tid);
        __syncthreads();
        mma_tile(AsP, Bsx, accP, wm, wn, gid, tig);
        mma_tile(AsG, Bsx, accG, wm, wn, gid, tig);
        __syncthreads();
    }
    // store transposed into smem with bias + tf32 rounding
    #pragma unroll
    for (int mt = 0; mt < 4; mt++) {
        int r0 = wm + mt * 16 + gid, r1 = r0 + 8;
        float p0 = d_bias[128 + r0], p1 = d_bias[128 + r1];
        float g0 = d_bias[256 + r0], g1 = d_bias[256 + r1];
        #pragma unroll
        for (int nt = 0; nt < 4; nt++) {
            int cn = wn + nt * 8 + 2 * tig;
            phi_s[cn][r0]     = tf32r(accP[mt][nt][0] + p0);
            phi_s[cn + 1][r0] = tf32r(accP[mt][nt][1] + p0);
            phi_s[cn][r1]     = tf32r(accP[mt][nt][2] + p1);
            phi_s[cn + 1][r1] = tf32r(accP[mt][nt][3] + p1);
            g_s[cn][r0]       = tf32r(accG[mt][nt][0] + g0);
            g_s[cn + 1][r0]   = tf32r(accG[mt][nt][1] + g0);
            g_s[cn][r1]       = tf32r(accG[mt][nt][2] + g1);
            g_s[cn + 1][r1]   = tf32r(accG[mt][nt][3] + g1);
        }
    }
    __syncthreads();
    // stage 2: reuse accP as M accumulator
    #pragma unroll
    for (int mt = 0; mt < 4; mt++)
        #pragma unroll
        for (int nt = 0; nt < 4; nt++)
            #pragma unroll
            for (int v = 0; v < 4; v++) accP[mt][nt][v] = 0.0f;
    #pragma unroll 1
    for (int st = 0; st < 8; st++)
        mma_tile(phi_s + st * 16, g_s + st * 16, accP, wm, wn, gid, tig);
    store_tile(d_Mpart + (size_t)(b * MSPLIT + s) * INTER * INTER, INTER,
               nullptr, accP, wm, wn, gid, tig);
}

// ---------------- Kernel 3: reduce split partials, scale 1/N ----------------
__global__ __launch_bounds__(256) void mred_kernel()
{
    const int i = blockIdx.x * 256 + threadIdx.x;   // float4 index, 65536 total
    const int b = i >> 12, r = i & 4095;
    const float4* p = (const float4*)(d_Mpart + (size_t)b * MSPLIT * 16384) + r;
    float4 a = make_float4(0.f, 0.f, 0.f, 0.f);
    #pragma unroll
    for (int sp = 0; sp < MSPLIT; sp++) {
        float4 v = p[(size_t)sp * 4096];
        a.x += v.x; a.y += v.y; a.z += v.z; a.w += v.w;
    }
    const float inv = 1.0f / (float)NN;
    ((float4*)(d_Mred + (size_t)b * 16384))[r] =
        make_float4(a.x * inv, a.y * inv, a.z * inv, a.w * inv);
}

// ---------------- Kernel 4: Qt[k][c] = sum_d Mred[k][d] * Wt2[d][c] ----------------
__global__ __launch_bounds__(256, 2) void q_kernel()
{
    __shared__ float As[16][136], Bs[16][136];
    float acc[4][4][4] = {};
    WARP_IDX
    const int b = blockIdx.y, n0 = blockIdx.x * 128;
    const float* M = d_Mred + (size_t)b * INTER * INTER;
    #pragma unroll 1
    for (int st = 0; st < 8; st++) {
        ld_tt(As, M + st * 16, INTER, tid);
        ld_nn(Bs, d_Wt2 + (size_t)st * 16 * CC + n0, CC, tid);
        __syncthreads();
        mma_tile(As, Bs, acc, wm, wn, gid, tig);
        __syncthreads();
    }
    store_tile(d_Qt + (size_t)b * INTER * CC + n0, CC, nullptr, acc, wm, wn, gid, tig);
}

// ---------------- Kernel 5: z (all 256 channels per block) + BN partial stats ----------------
__global__ __launch_bounds__(256, 1) void z_kernel(const float* __restrict__ W_b)
{
    __shared__ float As0[16][136], As1[16][136], Bs[16][136];
    float acc0[4][4][4] = {}, acc1[4][4][4] = {};
    WARP_IDX
    const int b = blockIdx.y, n0 = blockIdx.x * 128;
    const float* A = d_Qt + (size_t)b * INTER * CC;     // [k][c]
    const float* B = d_theta + (size_t)b * INTER * NN + n0;
    #pragma unroll 1
    for (int st = 0; st < 8; st++) {
        ld_nn(As0, A + (size_t)st * 16 * CC, CC, tid);
        ld_nn(As1, A + (size_t)st * 16 * CC + 128, CC, tid);
        ld_nn(Bs,  B + (size_t)st * 16 * NN, NN, tid);
        __syncthreads();
        mma_tile(As0, Bs, acc0, wm, wn, gid, tig);
        mma_tile(As1, Bs, acc1, wm, wn, gid, tig);
        __syncthreads();
    }
    float* zb = d_z + (size_t)b * CC * NN + n0;
    #pragma unroll
    for (int slab = 0; slab < 2; slab++) {
        float (&A4)[4][4][4] = slab ? acc1 : acc0;
        const float* bias = W_b + slab * 128;
        #pragma unroll
        for (int mt = 0; mt < 4; mt++) {
            int r0 = wm + mt * 16 + gid, r1 = r0 + 8;
            float b0 = bias[r0], b1 = bias[r1];
            float s0 = 0.f, q0 = 0.f, s1 = 0.f, q1 = 0.f;
            #pragma unroll
            for (int nt = 0; nt < 4; nt++) {
                int cn = wn + nt * 8 + 2 * tig;
                float v00 = A4[mt][nt][0] + b0, v01 = A4[mt][nt][1] + b0;
                float v10 = A4[mt][nt][2] + b1, v11 = A4[mt][nt][3] + b1;
                *(float2*)(zb + (size_t)(slab * 128 + r0) * NN + cn) = make_float2(v00, v01);
                *(float2*)(zb + (size_t)(slab * 128 + r1) * NN + cn) = make_float2(v10, v11);
                s0 += v00 + v01;  q0 += v00 * v00 + v01 * v01;
                s1 += v10 + v11;  q1 += v10 * v10 + v11 * v11;
            }
            // reduce over tig (lanes gid*4 + tig are consecutive)
            s0 += __shfl_xor_sync(~0u, s0, 1); s0 += __shfl_xor_sync(~0u, s0, 2);
            q0 += __shfl_xor_sync(~0u, q0, 1); q0 += __shfl_xor_sync(~0u, q0, 2);
            s1 += __shfl_xor_sync(~0u, s1, 1); s1 += __shfl_xor_sync(~0u, s1, 2);
            q1 += __shfl_xor_sync(~0u, q1, 1); q1 += __shfl_xor_sync(~0u, q1, 2);
            if (tig == 0) {
                int c0 = slab * 128 + r0, c1 = slab * 128 + r1;
                atomicAdd(&d_sums[c0], s0);       atomicAdd(&d_sums[256 + c0], q0);
                atomicAdd(&d_sums[c1], s1);       atomicAdd(&d_sums[256 + c1], q1);
            }
        }
    }
}

// ---------------- Kernel 6: finalize BN scale/shift ----------------
__global__ __launch_bounds__(256) void bn_finalize_kernel(
    const float* __restrict__ gamma, const float* __restrict__ beta)
{
    const int c = threadIdx.x;
    const float inv = 1.0f / (float)(BB * NN);
    float mean = d_sums[c] * inv;
    float var  = d_sums[256 + c] * inv - mean * mean;
    float sc   = gamma[c] * rsqrtf(var + 1e-5f);
    d_stats[2 * c]     = sc;
    d_stats[2 * c + 1] = beta[c] - mean * sc;
}

// ---------------- Kernel 7: out = z*scale + shift + x ----------------
__global__ __launch_bounds__(256) void bn_apply_kernel(
    const float* __restrict__ x, float* __restrict__ out)
{
    const size_t i = (size_t)blockIdx.x * 256 + threadIdx.x;  // float4 index
    const int c = (int)((i >> 9) & (CC - 1));
    const float sc = d_stats[2 * c];
    const float sh = d_stats[2 * c + 1];
    float4 zv = ((const float4*)d_z)[i];
    float4 xv = ((const float4*)x)[i];
    float4 o;
    o.x = zv.x * sc + sh + xv.x;
    o.y = zv.y * sc + sh + xv.y;
    o.z = zv.z * sc + sh + xv.z;
    o.w = zv.w * sc + sh + xv.w;
    ((float4*)out)[i] = o;
}

// ---------------- launch ----------------
extern "C" void kernel_launch(void* const* d_in, const int* in_sizes, int n_in,
                              void* d_out, int out_size)
{
    const float* x       = (const float*)d_in[0];
    const float* g_w     = (const float*)d_in[1];
    const float* g_b     = (const float*)d_in[2];
    const float* theta_w = (const float*)d_in[3];
    const float* theta_b = (const float*)d_in[4];
    const float* phi_w   = (const float*)d_in[5];
    const float* phi_b   = (const float*)d_in[6];
    const float* W_w     = (const float*)d_in[7];
    const float* W_b     = (const float*)d_in[8];
    const float* gamma   = (const float*)d_in[9];
    const float* beta    = (const float*)d_in[10];
    float* out = (float*)d_out;

    const int mpg_smem = (16 * 3 + 256) * 136 * 4;   // 165376 bytes
    static bool attr_set = false;
    if (!attr_set) {
        cudaFuncSetAttribute(mpg_kernel, cudaFuncAttributeMaxDynamicSharedMemorySize, mpg_smem);
        attr_set = true;
    }

    pack_kernel       <<<384, 256>>>(theta_w, theta_b, phi_w, phi_b, g_w, g_b, W_w);
    theta_kernel      <<<dim3(NN / 128, BB), 256>>>(x);
    mpg_kernel        <<<dim3(MSPLIT, BB), 256, mpg_smem>>>(x);
    mred_kernel       <<<256, 256>>>();
    q_kernel          <<<dim3(2, BB), 256>>>();
    z_kernel          <<<dim3(NN / 128, BB), 256>>>(W_b);
    bn_finalize_kernel<<<1, 256>>>(gamma, beta);
    bn_apply_kernel   <<<(size_t)(BB * CC * NN) / 4 / 256, 256>>>(x, out);
}

// round 5
// speedup vs baseline: 2.4995x; 1.0158x over previous
#include <cuda_runtime.h>
#include <cstdint>

#define BB    16
#define CC    256
#define INTER 128
#define NN    2048
#define MSPLIT 16

// ---------------- scratch ----------------
__device__ uint32_t d_Wtp [128 * 384];                // bf16 pairs along k: [k2][m] m=theta|phi|g
__device__ float    d_Wt2 [128 * 256];                // W_w^T fp32: [d][c]
__device__ float    d_bias[384];
__device__ uint32_t d_theta[(size_t)BB * INTER * (NN / 2)];   // bf16 pairs along n: [b][k][n2]
__device__ float    d_Mpart[(size_t)BB * MSPLIT * INTER * INTER];
__device__ float    d_Mred [(size_t)BB * INTER * INTER];
__device__ float    d_Qt   [(size_t)BB * INTER * CC]; // [b][k][c]
__device__ float    d_z    [(size_t)BB * CC * NN];
__device__ float    d_sums [512];
__device__ float    d_stats[2 * CC];

// ---------------- helpers ----------------
__device__ __forceinline__ uint32_t bf2(float lo, float hi) {
    uint32_t r; asm("cvt.rn.bf16x2.f32 %0,%1,%2;" : "=r"(r) : "f"(hi), "f"(lo));
    return r;
}
__device__ __forceinline__ void mma16(float* c, const uint32_t* a, const uint32_t* b) {
    asm volatile("mma.sync.aligned.m16n8k16.row.col.f32.bf16.bf16.f32 "
        "{%0,%1,%2,%3},{%4,%5,%6,%7},{%8,%9},{%0,%1,%2,%3};"
        : "+f"(c[0]), "+f"(c[1]), "+f"(c[2]), "+f"(c[3])
        : "r"(a[0]), "r"(a[1]), "r"(a[2]), "r"(a[3]), "r"(b[0]), "r"(b[1]));
}
// tf32 (q kernel only)
__device__ __forceinline__ float tf32r(float f) {
    uint32_t r; asm("cvt.rna.tf32.f32 %0,%1;" : "=r"(r) : "f"(f));
    return __uint_as_float(r);
}
__device__ __forceinline__ void mma8(float* c, const uint32_t* a, const uint32_t* b) {
    asm volatile("mma.sync.aligned.m16n8k8.row.col.f32.tf32.tf32.f32 "
        "{%0,%1,%2,%3},{%4,%5,%6,%7},{%8,%9},{%0,%1,%2,%3};"
        : "+f"(c[0]), "+f"(c[1]), "+f"(c[2]), "+f"(c[3])
        : "r"(a[0]), "r"(a[1]), "r"(a[2]), "r"(a[3]), "r"(b[0]), "r"(b[1]));
}

// ---------------- bf16-pair loaders (tile = 16 k x 128 cols as S[k2][col]) ----------------
// from fp32 global: pairs = rows (2k2, 2k2+1)
__device__ __forceinline__ void ld_pair_f32(uint32_t (*S)[136], const float* src, size_t ld, int tid)
{
    int k2 = tid >> 5, c = (tid & 31) * 4;
    const float* p = src + (size_t)(2 * k2) * ld + c;
    float4 u = *(const float4*)p;
    float4 v = *(const float4*)(p + ld);
    S[k2][c + 0] = bf2(u.x, v.x);
    S[k2][c + 1] = bf2(u.y, v.y);
    S[k2][c + 2] = bf2(u.z, v.z);
    S[k2][c + 3] = bf2(u.w, v.w);
}
// straight copy of pre-packed pairs
__device__ __forceinline__ void ld_pair_cp(uint32_t (*S)[136], const uint32_t* src, size_t ldw, int tid)
{
    int k2 = tid >> 5, c = (tid & 31) * 4;
    *(uint4*)&S[k2][c] = *(const uint4*)(src + (size_t)k2 * ldw + c);
}
// from bf16 global stored [k][n2-pairs-along-n]: interleave rows 2k2,2k2+1 into pairs along k
__device__ __forceinline__ void ld_pair_bf(uint32_t (*S)[136], const uint32_t* src, size_t ldw, int tid)
{
    int k2 = tid >> 5, c2 = (tid & 31) * 2;
    const uint32_t* p = src + (size_t)(2 * k2) * ldw + c2;
    uint32_t w00 = p[0], w01 = p[1];
    uint32_t w10 = p[ldw], w11 = p[ldw + 1];
    S[k2][c2 * 2 + 0] = __byte_perm(w00, w10, 0x5410);
    S[k2][c2 * 2 + 1] = __byte_perm(w00, w10, 0x7632);
    S[k2][c2 * 2 + 2] = __byte_perm(w01, w11, 0x5410);
    S[k2][c2 * 2 + 3] = __byte_perm(w01, w11, 0x7632);
}

// ---------------- 128x128 bf16 mma over one 16-k slab ----------------
__device__ __forceinline__ void mma_tile16(
    const uint32_t (*As)[136], const uint32_t (*Bs)[136],
    float (&acc)[4][4][4], int wm, int wn, int gid, int tig)
{
    uint32_t a[4][4], b[4][2];
    #pragma unroll
    for (int mt = 0; mt < 4; mt++) {
        int row = wm + mt * 16 + gid;
        a[mt][0] = As[tig][row];
        a[mt][1] = As[tig][row + 8];
        a[mt][2] = As[tig + 4][row];
        a[mt][3] = As[tig + 4][row + 8];
    }
    #pragma unroll
    for (int nt = 0; nt < 4; nt++) {
        int cn = wn + nt * 8 + gid;
        b[nt][0] = Bs[tig][cn];
        b[nt][1] = Bs[tig + 4][cn];
    }
    #pragma unroll
    for (int mt = 0; mt < 4; mt++)
        #pragma unroll
        for (int nt = 0; nt < 4; nt++)
            mma16(acc[mt][nt], a[mt], b[nt]);
}

// fp32 row-major C store (optional bias)
__device__ __forceinline__ void store_tile(
    float* C, size_t ldc, const float* bias,
    float (&acc)[4][4][4], int wm, int wn, int gid, int tig)
{
    #pragma unroll
    for (int mt = 0; mt < 4; mt++) {
        int r0 = wm + mt * 16 + gid, r1 = r0 + 8;
        float b0 = bias ? bias[r0] : 0.0f;
        float b1 = bias ? bias[r1] : 0.0f;
        #pragma unroll
        for (int nt = 0; nt < 4; nt++) {
            int cn = wn + nt * 8 + 2 * tig;
            *(float2*)(C + (size_t)r0 * ldc + cn) =
                make_float2(acc[mt][nt][0] + b0, acc[mt][nt][1] + b0);
            *(float2*)(C + (size_t)r1 * ldc + cn) =
                make_float2(acc[mt][nt][2] + b1, acc[mt][nt][3] + b1);
        }
    }
}

#define WARP_IDX \
    const int tid = threadIdx.x; \
    const int wid = tid >> 5; \
    const int wm = (wid >> 2) * 64, wn = (wid & 3) * 32; \
    const int gid = (tid & 31) >> 2, tig = tid & 3;

// ---------------- Kernel 0: pack weights + zero sums ----------------
__global__ __launch_bounds__(256) void pack_kernel(
    const float* __restrict__ tw, const float* __restrict__ tb,
    const float* __restrict__ pw, const float* __restrict__ pb,
    const float* __restrict__ gw, const float* __restrict__ gb,
    const float* __restrict__ Ww)
{
    int i = blockIdx.x * 256 + threadIdx.x;   // 0 .. 49151
    {
        int k2 = i / 384, m = i - k2 * 384;
        const float* w = (m < 128) ? tw : (m < 256) ? pw : gw;
        float2 v = *(const float2*)(w + (size_t)(m & 127) * 256 + 2 * k2);
        d_Wtp[i] = bf2(v.x, v.y);
    }
    if (i < 128 * 256) {
        int d = i >> 8, c = i & 255;
        d_Wt2[i] = Ww[(size_t)c * 128 + d];
    }
    if (i < 384) d_bias[i] = (i < 128) ? tb[i] : (i < 256) ? pb[i - 128] : gb[i - 256];
    if (i < 512) d_sums[i] = 0.0f;
}

// ---------------- Kernel 1: theta -> bf16-packed [k][n2] ----------------
__global__ __launch_bounds__(256, 2) void theta_kernel(const float* __restrict__ x)
{
    __shared__ uint32_t As[8][136], Bs[8][136];
    float acc[4][4][4] = {};
    WARP_IDX
    const int b = blockIdx.y, n0 = blockIdx.x * 128;
    const float* B = x + (size_t)b * CC * NN + n0;
    #pragma unroll 1
    for (int st = 0; st < 16; st++) {
        ld_pair_cp(As, d_Wtp + (size_t)st * 8 * 384, 384, tid);
        ld_pair_f32(Bs, B + (size_t)st * 16 * NN, NN, tid);
        __syncthreads();
        mma_tile16(As, Bs, acc, wm, wn, gid, tig);
        __syncthreads();
    }
    uint32_t* T = d_theta + (size_t)b * INTER * (NN / 2) + n0 / 2;
    #pragma unroll
    for (int mt = 0; mt < 4; mt++) {
        int r0 = wm + mt * 16 + gid, r1 = r0 + 8;
        float b0 = d_bias[r0], b1 = d_bias[r1];
        #pragma unroll
        for (int nt = 0; nt < 4; nt++) {
            int cw = (wn + nt * 8 + 2 * tig) >> 1;
            T[(size_t)r0 * (NN / 2) + cw] = bf2(acc[mt][nt][0] + b0, acc[mt][nt][1] + b0);
            T[(size_t)r1 * (NN / 2) + cw] = bf2(acc[mt][nt][2] + b1, acc[mt][nt][3] + b1);
        }
    }
}

// ---------------- Kernel 2: fused phi/g projection + M partial (bf16) ----------------
__global__ __launch_bounds__(256, 1) void mpg_kernel(const float* __restrict__ x)
{
    extern __shared__ uint32_t sm32[];
    uint32_t (*AsP)[136]  = (uint32_t(*)[136])sm32;   // 8 rows
    uint32_t (*AsG)[136]  = AsP + 8;
    uint32_t (*Bsx)[136]  = AsG + 8;
    uint32_t (*phi_s)[136] = Bsx + 8;                  // 64 rows: [n2][k]
    uint32_t (*g_s)[136]   = phi_s + 64;               // 64 rows: [n2][d]
    WARP_IDX
    const int b = blockIdx.y, s = blockIdx.x;
    const float* B = x + (size_t)b * CC * NN + s * 128;

    float accP[4][4][4] = {}, accG[4][4][4] = {};
    #pragma unroll 1
    for (int st = 0; st < 16; st++) {
        ld_pair_cp(AsP, d_Wtp + (size_t)st * 8 * 384 + 128, 384, tid);
        ld_pair_cp(AsG, d_Wtp + (size_t)st * 8 * 384 + 256, 384, tid);
        ld_pair_f32(Bsx, B + (size_t)st * 16 * NN, NN, tid);
        __syncthreads();
        mma_tile16(AsP, Bsx, accP, wm, wn, gid, tig);
        mma_tile16(AsG, Bsx, accG, wm, wn, gid, tig);
        __syncthreads();
    }
    // write phi/g transposed into smem as bf16 pairs along n
    #pragma unroll
    for (int mt = 0; mt < 4; mt++) {
        int r0 = wm + mt * 16 + gid, r1 = r0 + 8;
        float p0 = d_bias[128 + r0], p1 = d_bias[128 + r1];
        float q0 = d_bias[256 + r0], q1 = d_bias[256 + r1];
        #pragma unroll
        for (int nt = 0; nt < 4; nt++) {
            int n2 = (wn + nt * 8 + 2 * tig) >> 1;
            phi_s[n2][r0] = bf2(accP[mt][nt][0] + p0, accP[mt][nt][1] + p0);
            phi_s[n2][r1] = bf2(accP[mt][nt][2] + p1, accP[mt][nt][3] + p1);
            g_s[n2][r0]   = bf2(accG[mt][nt][0] + q0, accG[mt][nt][1] + q0);
            g_s[n2][r1]   = bf2(accG[mt][nt][2] + q1, accG[mt][nt][3] + q1);
        }
    }
    __syncthreads();
    // stage 2: Mpart[k][d] = sum_n phi[k,n] g[d,n]
    #pragma unroll
    for (int mt = 0; mt < 4; mt++)
        #pragma unroll
        for (int nt = 0; nt < 4; nt++)
            #pragma unroll
            for (int v = 0; v < 4; v++) accP[mt][nt][v] = 0.0f;
    #pragma unroll 1
    for (int s2 = 0; s2 < 8; s2++)
        mma_tile16(phi_s + s2 * 8, g_s + s2 * 8, accP, wm, wn, gid, tig);
    store_tile(d_Mpart + (size_t)(b * MSPLIT + s) * INTER * INTER, INTER,
               nullptr, accP, wm, wn, gid, tig);
}

// ---------------- Kernel 3: reduce split partials, scale 1/N ----------------
__global__ __launch_bounds__(256) void mred_kernel()
{
    const int i = blockIdx.x * 256 + threadIdx.x;   // float4 index, 65536 total
    const int b = i >> 12, r = i & 4095;
    const float4* p = (const float4*)(d_Mpart + (size_t)b * MSPLIT * 16384) + r;
    float4 a = make_float4(0.f, 0.f, 0.f, 0.f);
    #pragma unroll
    for (int sp = 0; sp < MSPLIT; sp++) {
        float4 v = p[(size_t)sp * 4096];
        a.x += v.x; a.y += v.y; a.z += v.z; a.w += v.w;
    }
    const float inv = 1.0f / (float)NN;
    ((float4*)(d_Mred + (size_t)b * 16384))[r] =
        make_float4(a.x * inv, a.y * inv, a.z * inv, a.w * inv);
}

// ---------------- Kernel 4 (tf32): Qt[k][c] = sum_d Mred[k][d] * Wt2[d][c] ----------------
__device__ __forceinline__ void ld_nn(float (*S)[136], const float* src, size_t ld, int tid)
{
    int k = tid >> 4, c = (tid & 15) * 8;
    const float* p = src + (size_t)k * ld + c;
    float4 v0 = *(const float4*)p, v1 = *(const float4*)(p + 4);
    S[k][c + 0] = tf32r(v0.x); S[k][c + 1] = tf32r(v0.y);
    S[k][c + 2] = tf32r(v0.z); S[k][c + 3] = tf32r(v0.w);
    S[k][c + 4] = tf32r(v1.x); S[k][c + 5] = tf32r(v1.y);
    S[k][c + 6] = tf32r(v1.z); S[k][c + 7] = tf32r(v1.w);
}
__device__ __forceinline__ void ld_tt(float (*S)[136], const float* src, size_t ld, int tid)
{
    int r = tid >> 1, q = (tid & 1) * 8;
    const float* p = src + (size_t)r * ld + q;
    float4 v0 = *(const float4*)p, v1 = *(const float4*)(p + 4);
    S[q + 0][r] = tf32r(v0.x); S[q + 1][r] = tf32r(v0.y);
    S[q + 2][r] = tf32r(v0.z); S[q + 3][r] = tf32r(v0.w);
    S[q + 4][r] = tf32r(v1.x); S[q + 5][r] = tf32r(v1.y);
    S[q + 6][r] = tf32r(v1.z); S[q + 7][r] = tf32r(v1.w);
}
__device__ __forceinline__ void mma_tile8(
    const float (*As)[136], const float (*Bs)[136],
    float (&acc)[4][4][4], int wm, int wn, int gid, int tig)
{
    #pragma unroll
    for (int ks = 0; ks < 2; ks++) {
        uint32_t a[4][4], b[4][2];
        const int kc = ks * 8 + tig;
        #pragma unroll
        for (int mt = 0; mt < 4; mt++) {
            int row = wm + mt * 16 + gid;
            a[mt][0] = __float_as_uint(As[kc][row]);
            a[mt][1] = __float_as_uint(As[kc][row + 8]);
            a[mt][2] = __float_as_uint(As[kc + 4][row]);
            a[mt][3] = __float_as_uint(As[kc + 4][row + 8]);
        }
        #pragma unroll
        for (int nt = 0; nt < 4; nt++) {
            int cn = wn + nt * 8 + gid;
            b[nt][0] = __float_as_uint(Bs[kc][cn]);
            b[nt][1] = __float_as_uint(Bs[kc + 4][cn]);
        }
        #pragma unroll
        for (int mt = 0; mt < 4; mt++)
            #pragma unroll
            for (int nt = 0; nt < 4; nt++)
                mma8(acc[mt][nt], a[mt], b[nt]);
    }
}
__global__ __launch_bounds__(256, 2) void q_kernel()
{
    __shared__ float As[16][136], Bs[16][136];
    float acc[4][4][4] = {};
    WARP_IDX
    const int b = blockIdx.y, n0 = blockIdx.x * 128;
    const float* M = d_Mred + (size_t)b * INTER * INTER;
    #pragma unroll 1
    for (int st = 0; st < 8; st++) {
        ld_tt(As, M + st * 16, INTER, tid);
        ld_nn(Bs, d_Wt2 + (size_t)st * 16 * CC + n0, CC, tid);
        __syncthreads();
        mma_tile8(As, Bs, acc, wm, wn, gid, tig);
        __syncthreads();
    }
    store_tile(d_Qt + (size_t)b * INTER * CC + n0, CC, nullptr, acc, wm, wn, gid, tig);
}

// ---------------- Kernel 5: z = Q @ theta + W_b, with BN partial stats ----------------
__global__ __launch_bounds__(256, 2) void z_kernel(const float* __restrict__ W_b)
{
    __shared__ uint32_t As[8][136], Bs[8][136];
    float acc[4][4][4] = {};
    WARP_IDX
    const int b = blockIdx.z, m0 = blockIdx.y * 128, n0 = blockIdx.x * 128;
    const float* A = d_Qt + (size_t)b * INTER * CC + m0;            // [k][c]
    const uint32_t* B = d_theta + (size_t)b * INTER * (NN / 2) + n0 / 2;
    #pragma unroll 1
    for (int st = 0; st < 8; st++) {
        ld_pair_f32(As, A + (size_t)st * 16 * CC, CC, tid);
        ld_pair_bf(Bs, B + (size_t)st * 16 * (NN / 2), NN / 2, tid);
        __syncthreads();
        mma_tile16(As, Bs, acc, wm, wn, gid, tig);
        __syncthreads();
    }
    float* zb = d_z + ((size_t)b * CC + m0) * NN + n0;
    #pragma unroll
    for (int mt = 0; mt < 4; mt++) {
        int r0 = wm + mt * 16 + gid, r1 = r0 + 8;
        float b0 = W_b[m0 + r0], b1 = W_b[m0 + r1];
        float s0 = 0.f, q0 = 0.f, s1 = 0.f, q1 = 0.f;
        #pragma unroll
        for (int nt = 0; nt < 4; nt++) {
            int cn = wn + nt * 8 + 2 * tig;
            float v00 = acc[mt][nt][0] + b0, v01 = acc[mt][nt][1] + b0;
            float v10 = acc[mt][nt][2] + b1, v11 = acc[mt][nt][3] + b1;
            *(float2*)(zb + (size_t)r0 * NN + cn) = make_float2(v00, v01);
            *(float2*)(zb + (size_t)r1 * NN + cn) = make_float2(v10, v11);
            s0 += v00 + v01;  q0 += v00 * v00 + v01 * v01;
            s1 += v10 + v11;  q1 += v10 * v10 + v11 * v11;
        }
        s0 += __shfl_xor_sync(~0u, s0, 1); s0 += __shfl_xor_sync(~0u, s0, 2);
        q0 += __shfl_xor_sync(~0u, q0, 1); q0 += __shfl_xor_sync(~0u, q0, 2);
        s1 += __shfl_xor_sync(~0u, s1, 1); s1 += __shfl_xor_sync(~0u, s1, 2);
        q1 += __shfl_xor_sync(~0u, q1, 1); q1 += __shfl_xor_sync(~0u, q1, 2);
        if (tig == 0) {
            atomicAdd(&d_sums[m0 + r0], s0);       atomicAdd(&d_sums[256 + m0 + r0], q0);
            atomicAdd(&d_sums[m0 + r1], s1);       atomicAdd(&d_sums[256 + m0 + r1], q1);
        }
    }
}

// ---------------- Kernel 6: finalize BN ----------------
__global__ __launch_bounds__(256) void bn_finalize_kernel(
    const float* __restrict__ gamma, const float* __restrict__ beta)
{
    const int c = threadIdx.x;
    const float inv = 1.0f / (float)(BB * NN);
    float mean = d_sums[c] * inv;
    float var  = d_sums[256 + c] * inv - mean * mean;
    float sc   = gamma[c] * rsqrtf(var + 1e-5f);
    d_stats[2 * c]     = sc;
    d_stats[2 * c + 1] = beta[c] - mean * sc;
}

// ---------------- Kernel 7: out = z*scale + shift + x ----------------
__global__ __launch_bounds__(256) void bn_apply_kernel(
    const float* __restrict__ x, float* __restrict__ out)
{
    const size_t i = (size_t)blockIdx.x * 256 + threadIdx.x;  // float4 index
    const int c = (int)((i >> 9) & (CC - 1));
    const float sc = d_stats[2 * c];
    const float sh = d_stats[2 * c + 1];
    float4 zv = ((const float4*)d_z)[i];
    float4 xv = ((const float4*)x)[i];
    float4 o;
    o.x = zv.x * sc + sh + xv.x;
    o.y = zv.y * sc + sh + xv.y;
    o.z = zv.z * sc + sh + xv.z;
    o.w = zv.w * sc + sh + xv.w;
    ((float4*)out)[i] = o;
}

// ---------------- launch ----------------
extern "C" void kernel_launch(void* const* d_in, const int* in_sizes, int n_in,
                              void* d_out, int out_size)
{
    const float* x       = (const float*)d_in[0];
    const float* g_w     = (const float*)d_in[1];
    const float* g_b     = (const float*)d_in[2];
    const float* theta_w = (const float*)d_in[3];
    const float* theta_b = (const float*)d_in[4];
    const float* phi_w   = (const float*)d_in[5];
    const float* phi_b   = (const float*)d_in[6];
    const float* W_w     = (const float*)d_in[7];
    const float* W_b     = (const float*)d_in[8];
    const float* gamma   = (const float*)d_in[9];
    const float* beta    = (const float*)d_in[10];
    float* out = (float*)d_out;

    const int mpg_smem = (8 * 3 + 64 * 2) * 136 * 4;   // 82688 bytes
    static bool attr_set = false;
    if (!attr_set) {
        cudaFuncSetAttribute(mpg_kernel, cudaFuncAttributeMaxDynamicSharedMemorySize, mpg_smem);
        attr_set = true;
    }

    pack_kernel       <<<192, 256>>>(theta_w, theta_b, phi_w, phi_b, g_w, g_b, W_w);
    theta_kernel      <<<dim3(NN / 128, BB), 256>>>(x);
    mpg_kernel        <<<dim3(MSPLIT, BB), 256, mpg_smem>>>(x);
    mred_kernel       <<<256, 256>>>();
    q_kernel          <<<dim3(2, BB), 256>>>();
    z_kernel          <<<dim3(NN / 128, 2, BB), 256>>>(W_b);
    bn_finalize_kernel<<<1, 256>>>(gamma, beta);
    bn_apply_kernel   <<<(size_t)(BB * CC * NN) / 4 / 256, 256>>>(x, out);
}

// round 6
// speedup vs baseline: 4.0451x; 1.6184x over previous
#include <cuda_runtime.h>
#include <cstdint>

#define BB    16
#define CC    256
#define INTER 128
#define NN    2048
#define MSPLIT 16

// ---------------- scratch ----------------
__device__ uint32_t d_Wtp [128 * 384];                 // bf16 pairs along k: [k2][m], m = theta|phi|g
__device__ float    d_Wt2 [128 * 256];                 // W_w^T fp32: [d][c]
__device__ float    d_bias[384];
__device__ uint32_t d_theta[(size_t)BB * INTER * (NN / 2)];   // bf16 pairs along n: [b][k][n2]
__device__ float    d_Mpart[(size_t)BB * MSPLIT * INTER * INTER];
__device__ float    d_Mred [(size_t)BB * INTER * INTER];
__device__ float    d_Qt   [(size_t)BB * INTER * CC];  // [b][k][c]
__device__ uint32_t d_zb   [(size_t)BB * CC * (NN / 2)];      // z as bf16 pairs along n
__device__ float    d_sums [512];

// ---------------- helpers ----------------
__device__ __forceinline__ uint32_t bf2(float lo, float hi) {
    uint32_t r; asm("cvt.rn.bf16x2.f32 %0,%1,%2;" : "=r"(r) : "f"(hi), "f"(lo));
    return r;
}
__device__ __forceinline__ void mma16(float* c, const uint32_t* a, const uint32_t* b) {
    asm volatile("mma.sync.aligned.m16n8k16.row.col.f32.bf16.bf16.f32 "
        "{%0,%1,%2,%3},{%4,%5,%6,%7},{%8,%9},{%0,%1,%2,%3};"
        : "+f"(c[0]), "+f"(c[1]), "+f"(c[2]), "+f"(c[3])
        : "r"(a[0]), "r"(a[1]), "r"(a[2]), "r"(a[3]), "r"(b[0]), "r"(b[1]));
}
__device__ __forceinline__ float tf32r(float f) {
    uint32_t r; asm("cvt.rna.tf32.f32 %0,%1;" : "=r"(r) : "f"(f));
    return __uint_as_float(r);
}
__device__ __forceinline__ void mma8(float* c, const uint32_t* a, const uint32_t* b) {
    asm volatile("mma.sync.aligned.m16n8k8.row.col.f32.tf32.tf32.f32 "
        "{%0,%1,%2,%3},{%4,%5,%6,%7},{%8,%9},{%0,%1,%2,%3};"
        : "+f"(c[0]), "+f"(c[1]), "+f"(c[2]), "+f"(c[3])
        : "r"(a[0]), "r"(a[1]), "r"(a[2]), "r"(a[3]), "r"(b[0]), "r"(b[1]));
}

// ---------------- bf16 mma over one 16-k slab (As/Bs are [8][136] slabs) ----------------
__device__ __forceinline__ void mma_tile16(
    const uint32_t (*As)[136], const uint32_t (*Bs)[136],
    float (&acc)[4][4][4], int wm, int wn, int gid, int tig)
{
    uint32_t a[4][4], b[4][2];
    #pragma unroll
    for (int mt = 0; mt < 4; mt++) {
        int row = wm + mt * 16 + gid;
        a[mt][0] = As[tig][row];
        a[mt][1] = As[tig][row + 8];
        a[mt][2] = As[tig + 4][row];
        a[mt][3] = As[tig + 4][row + 8];
    }
    #pragma unroll
    for (int nt = 0; nt < 4; nt++) {
        int cn = wn + nt * 8 + gid;
        b[nt][0] = Bs[tig][cn];
        b[nt][1] = Bs[tig + 4][cn];
    }
    #pragma unroll
    for (int mt = 0; mt < 4; mt++)
        #pragma unroll
        for (int nt = 0; nt < 4; nt++)
            mma16(acc[mt][nt], a[mt], b[nt]);
}

// fp32 row-major C store (optional bias)
__device__ __forceinline__ void store_tile(
    float* C, size_t ldc, const float* bias,
    float (&acc)[4][4][4], int wm, int wn, int gid, int tig)
{
    #pragma unroll
    for (int mt = 0; mt < 4; mt++) {
        int r0 = wm + mt * 16 + gid, r1 = r0 + 8;
        float b0 = bias ? bias[r0] : 0.0f;
        float b1 = bias ? bias[r1] : 0.0f;
        #pragma unroll
        for (int nt = 0; nt < 4; nt++) {
            int cn = wn + nt * 8 + 2 * tig;
            *(float2*)(C + (size_t)r0 * ldc + cn) =
                make_float2(acc[mt][nt][0] + b0, acc[mt][nt][1] + b0);
            *(float2*)(C + (size_t)r1 * ldc + cn) =
                make_float2(acc[mt][nt][2] + b1, acc[mt][nt][3] + b1);
        }
    }
}

#define WARP_IDX \
    const int tid = threadIdx.x; \
    const int wid = tid >> 5; \
    const int wm = (wid >> 2) * 64, wn = (wid & 3) * 32; \
    const int gid = (tid & 31) >> 2, tig = tid & 3;

// ---------------- Kernel 0: pack weights + zero sums ----------------
__global__ __launch_bounds__(256) void pack_kernel(
    const float* __restrict__ tw, const float* __restrict__ tb,
    const float* __restrict__ pw, const float* __restrict__ pb,
    const float* __restrict__ gw, const float* __restrict__ gb,
    const float* __restrict__ Ww)
{
    int i = blockIdx.x * 256 + threadIdx.x;   // 0 .. 49151
    {
        int k2 = i / 384, m = i - k2 * 384;
        const float* w = (m < 128) ? tw : (m < 256) ? pw : gw;
        float2 v = *(const float2*)(w + (size_t)(m & 127) * 256 + 2 * k2);
        d_Wtp[i] = bf2(v.x, v.y);
    }
    if (i < 128 * 256) {
        int d = i >> 8, c = i & 255;
        d_Wt2[i] = Ww[(size_t)c * 128 + d];
    }
    if (i < 384) d_bias[i] = (i < 128) ? tb[i] : (i < 256) ? pb[i - 128] : gb[i - 256];
    if (i < 512) d_sums[i] = 0.0f;
}

// ---------------- Kernel 1: fused theta/phi/g projections + M partial ----------------
// smem: xs[128][136] (x slab bf16 k-pairs), wp[128][136] (weight panel, reused),
//       ps[64][136], gs[64][136] (phi/g transposed, bf16 n-pairs)
__global__ __launch_bounds__(256, 1) void proj_fused_kernel(const float* __restrict__ x)
{
    extern __shared__ uint32_t sm32[];
    uint32_t (*xs)[136] = (uint32_t(*)[136])sm32;          // 128 rows
    uint32_t (*wp)[136] = xs + 128;                        // 128 rows
    uint32_t (*ps)[136] = wp + 128;                        // 64 rows
    uint32_t (*gs)[136] = ps + 64;                         // 64 rows
    WARP_IDX
    const int b = blockIdx.y, s = blockIdx.x;
    const int n0 = s * 128;
    const float* xg = x + (size_t)b * CC * NN + n0;

    // load x slab: xs[k2][n] = bf2(x[2k2][n], x[2k2+1][n])
    {
        int c = (tid & 31) * 4, kb = tid >> 5;
        #pragma unroll
        for (int it = 0; it < 16; it++) {
            int k2 = kb + it * 8;
            const float* p = xg + (size_t)(2 * k2) * NN + c;
            float4 u = *(const float4*)p;
            float4 v = *(const float4*)(p + NN);
            xs[k2][c + 0] = bf2(u.x, v.x);
            xs[k2][c + 1] = bf2(u.y, v.y);
            xs[k2][c + 2] = bf2(u.z, v.z);
            xs[k2][c + 3] = bf2(u.w, v.w);
        }
    }
    // load theta weight panel
    {
        int m4 = (tid & 31) * 4, kb = tid >> 5;
        #pragma unroll
        for (int it = 0; it < 16; it++) {
            int k2 = kb + it * 8;
            *(uint4*)&wp[k2][m4] = *(const uint4*)(d_Wtp + (size_t)k2 * 384 + m4);
        }
    }
    __syncthreads();

    // ---- theta GEMM (sync-free mainloop) ----
    {
        float acc[4][4][4] = {};
        #pragma unroll 4
        for (int st = 0; st < 16; st++)
            mma_tile16(wp + st * 8, xs + st * 8, acc, wm, wn, gid, tig);
        uint32_t* T = d_theta + (size_t)b * INTER * (NN / 2) + n0 / 2;
        #pragma unroll
        for (int mt = 0; mt < 4; mt++) {
            int r0 = wm + mt * 16 + gid, r1 = r0 + 8;
            float b0 = d_bias[r0], b1 = d_bias[r1];
            #pragma unroll
            for (int nt = 0; nt < 4; nt++) {
                int cw = (wn + nt * 8 + 2 * tig) >> 1;
                T[(size_t)r0 * (NN / 2) + cw] = bf2(acc[mt][nt][0] + b0, acc[mt][nt][1] + b0);
                T[(size_t)r1 * (NN / 2) + cw] = bf2(acc[mt][nt][2] + b1, acc[mt][nt][3] + b1);
            }
        }
    }
    __syncthreads();
    // ---- phi panel + GEMM -> ps ----
    {
        int m4 = (tid & 31) * 4, kb = tid >> 5;
        #pragma unroll
        for (int it = 0; it < 16; it++) {
            int k2 = kb + it * 8;
            *(uint4*)&wp[k2][m4] = *(const uint4*)(d_Wtp + (size_t)k2 * 384 + 128 + m4);
        }
    }
    __syncthreads();
    {
        float acc[4][4][4] = {};
        #pragma unroll 4
        for (int st = 0; st < 16; st++)
            mma_tile16(wp + st * 8, xs + st * 8, acc, wm, wn, gid, tig);
        #pragma unroll
        for (int mt = 0; mt < 4; mt++) {
            int r0 = wm + mt * 16 + gid, r1 = r0 + 8;
            float b0 = d_bias[128 + r0], b1 = d_bias[128 + r1];
            #pragma unroll
            for (int nt = 0; nt < 4; nt++) {
                int n2 = (wn + nt * 8 + 2 * tig) >> 1;
                ps[n2][r0] = bf2(acc[mt][nt][0] + b0, acc[mt][nt][1] + b0);
                ps[n2][r1] = bf2(acc[mt][nt][2] + b1, acc[mt][nt][3] + b1);
            }
        }
    }
    __syncthreads();
    // ---- g panel + GEMM -> gs ----
    {
        int m4 = (tid & 31) * 4, kb = tid >> 5;
        #pragma unroll
        for (int it = 0; it < 16; it++) {
            int k2 = kb + it * 8;
            *(uint4*)&wp[k2][m4] = *(const uint4*)(d_Wtp + (size_t)k2 * 384 + 256 + m4);
        }
    }
    __syncthreads();
    {
        float acc[4][4][4] = {};
        #pragma unroll 4
        for (int st = 0; st < 16; st++)
            mma_tile16(wp + st * 8, xs + st * 8, acc, wm, wn, gid, tig);
        #pragma unroll
        for (int mt = 0; mt < 4; mt++) {
            int r0 = wm + mt * 16 + gid, r1 = r0 + 8;
            float b0 = d_bias[256 + r0], b1 = d_bias[256 + r1];
            #pragma unroll
            for (int nt = 0; nt < 4; nt++) {
                int n2 = (wn + nt * 8 + 2 * tig) >> 1;
                gs[n2][r0] = bf2(acc[mt][nt][0] + b0, acc[mt][nt][1] + b0);
                gs[n2][r1] = bf2(acc[mt][nt][2] + b1, acc[mt][nt][3] + b1);
            }
        }
    }
    __syncthreads();
    // ---- M partial: Mpart[k][d] = sum_n phi[k,n] g[d,n] ----
    {
        float acc[4][4][4] = {};
        #pragma unroll 4
        for (int s2 = 0; s2 < 8; s2++)
            mma_tile16(ps + s2 * 8, gs + s2 * 8, acc, wm, wn, gid, tig);
        store_tile(d_Mpart + (size_t)(b * MSPLIT + s) * INTER * INTER, INTER,
                   nullptr, acc, wm, wn, gid, tig);
    }
}

// ---------------- Kernel 2: reduce split partials, scale 1/N ----------------
__global__ __launch_bounds__(256) void mred_kernel()
{
    const int i = blockIdx.x * 256 + threadIdx.x;   // float4 index, 65536 total
    const int b = i >> 12, r = i & 4095;
    const float4* p = (const float4*)(d_Mpart + (size_t)b * MSPLIT * 16384) + r;
    float4 a = make_float4(0.f, 0.f, 0.f, 0.f);
    #pragma unroll
    for (int sp = 0; sp < MSPLIT; sp++) {
        float4 v = p[(size_t)sp * 4096];
        a.x += v.x; a.y += v.y; a.z += v.z; a.w += v.w;
    }
    const float inv = 1.0f / (float)NN;
    ((float4*)(d_Mred + (size_t)b * 16384))[r] =
        make_float4(a.x * inv, a.y * inv, a.z * inv, a.w * inv);
}

// ---------------- Kernel 3 (tf32): Qt[k][c] = sum_d Mred[k][d] * Wt2[d][c] ----------------
__device__ __forceinline__ void ld_nn(float (*S)[136], const float* src, size_t ld, int tid)
{
    int k = tid >> 4, c = (tid & 15) * 8;
    const float* p = src + (size_t)k * ld + c;
    float4 v0 = *(const float4*)p, v1 = *(const float4*)(p + 4);
    S[k][c + 0] = tf32r(v0.x); S[k][c + 1] = tf32r(v0.y);
    S[k][c + 2] = tf32r(v0.z); S[k][c + 3] = tf32r(v0.w);
    S[k][c + 4] = tf32r(v1.x); S[k][c + 5] = tf32r(v1.y);
    S[k][c + 6] = tf32r(v1.z); S[k][c + 7] = tf32r(v1.w);
}
__device__ __forceinline__ void ld_tt(float (*S)[136], const float* src, size_t ld, int tid)
{
    int r = tid >> 1, q = (tid & 1) * 8;
    const float* p = src + (size_t)r * ld + q;
    float4 v0 = *(const float4*)p, v1 = *(const float4*)(p + 4);
    S[q + 0][r] = tf32r(v0.x); S[q + 1][r] = tf32r(v0.y);
    S[q + 2][r] = tf32r(v0.z); S[q + 3][r] = tf32r(v0.w);
    S[q + 4][r] = tf32r(v1.x); S[q + 5][r] = tf32r(v1.y);
    S[q + 6][r] = tf32r(v1.z); S[q + 7][r] = tf32r(v1.w);
}
__device__ __forceinline__ void mma_tile8(
    const float (*As)[136], const float (*Bs)[136],
    float (&acc)[4][4][4], int wm, int wn, int gid, int tig)
{
    #pragma unroll
    for (int ks = 0; ks < 2; ks++) {
        uint32_t a[4][4], b[4][2];
        const int kc = ks * 8 + tig;
        #pragma unroll
        for (int mt = 0; mt < 4; mt++) {
            int row = wm + mt * 16 + gid;
            a[mt][0] = __float_as_uint(As[kc][row]);
            a[mt][1] = __float_as_uint(As[kc][row + 8]);
            a[mt][2] = __float_as_uint(As[kc + 4][row]);
            a[mt][3] = __float_as_uint(As[kc + 4][row + 8]);
        }
        #pragma unroll
        for (int nt = 0; nt < 4; nt++) {
            int cn = wn + nt * 8 + gid;
            b[nt][0] = __float_as_uint(Bs[kc][cn]);
            b[nt][1] = __float_as_uint(Bs[kc + 4][cn]);
        }
        #pragma unroll
        for (int mt = 0; mt < 4; mt++)
            #pragma unroll
            for (int nt = 0; nt < 4; nt++)
                mma8(acc[mt][nt], a[mt], b[nt]);
    }
}
__global__ __launch_bounds__(256, 2) void q_kernel()
{
    __shared__ float As[16][136], Bs[16][136];
    float acc[4][4][4] = {};
    WARP_IDX
    const int b = blockIdx.y, n0 = blockIdx.x * 128;
    const float* M = d_Mred + (size_t)b * INTER * INTER;
    #pragma unroll 1
    for (int st = 0; st < 8; st++) {
        ld_tt(As, M + st * 16, INTER, tid);
        ld_nn(Bs, d_Wt2 + (size_t)st * 16 * CC + n0, CC, tid);
        __syncthreads();
        mma_tile8(As, Bs, acc, wm, wn, gid, tig);
        __syncthreads();
    }
    store_tile(d_Qt + (size_t)b * INTER * CC + n0, CC, nullptr, acc, wm, wn, gid, tig);
}

// ---------------- bf16-pair loaders for z ----------------
__device__ __forceinline__ void ld_pair_f32(uint32_t (*S)[136], const float* src, size_t ld, int tid)
{
    int k2 = tid >> 5, c = (tid & 31) * 4;
    const float* p = src + (size_t)(2 * k2) * ld + c;
    float4 u = *(const float4*)p;
    float4 v = *(const float4*)(p + ld);
    S[k2][c + 0] = bf2(u.x, v.x);
    S[k2][c + 1] = bf2(u.y, v.y);
    S[k2][c + 2] = bf2(u.z, v.z);
    S[k2][c + 3] = bf2(u.w, v.w);
}
__device__ __forceinline__ void ld_pair_bf(uint32_t (*S)[136], const uint32_t* src, size_t ldw, int tid)
{
    int k2 = tid >> 5, c2 = (tid & 31) * 2;
    const uint32_t* p = src + (size_t)(2 * k2) * ldw + c2;
    uint32_t w00 = p[0], w01 = p[1];
    uint32_t w10 = p[ldw], w11 = p[ldw + 1];
    S[k2][c2 * 2 + 0] = __byte_perm(w00, w10, 0x5410);
    S[k2][c2 * 2 + 1] = __byte_perm(w00, w10, 0x7632);
    S[k2][c2 * 2 + 2] = __byte_perm(w01, w11, 0x5410);
    S[k2][c2 * 2 + 3] = __byte_perm(w01, w11, 0x7632);
}

// ---------------- Kernel 4: z = Q @ theta + W_b (bf16 out) + BN partial stats ----------------
__global__ __launch_bounds__(256, 2) void z_kernel(const float* __restrict__ W_b)
{
    __shared__ uint32_t As[8][136], Bs[8][136];
    float acc[4][4][4] = {};
    WARP_IDX
    const int b = blockIdx.z, m0 = blockIdx.y * 128, n0 = blockIdx.x * 128;
    const float* A = d_Qt + (size_t)b * INTER * CC + m0;            // [k][c]
    const uint32_t* B = d_theta + (size_t)b * INTER * (NN / 2) + n0 / 2;
    #pragma unroll 1
    for (int st = 0; st < 8; st++) {
        ld_pair_f32(As, A + (size_t)st * 16 * CC, CC, tid);
        ld_pair_bf(Bs, B + (size_t)st * 16 * (NN / 2), NN / 2, tid);
        __syncthreads();
        mma_tile16(As, Bs, acc, wm, wn, gid, tig);
        __syncthreads();
    }
    uint32_t* zb = d_zb + ((size_t)b * CC + m0) * (NN / 2) + n0 / 2;
    #pragma unroll
    for (int mt = 0; mt < 4; mt++) {
        int r0 = wm + mt * 16 + gid, r1 = r0 + 8;
        float b0 = W_b[m0 + r0], b1 = W_b[m0 + r1];
        float s0 = 0.f, q0 = 0.f, s1 = 0.f, q1 = 0.f;
        #pragma unroll
        for (int nt = 0; nt < 4; nt++) {
            int cn = wn + nt * 8 + 2 * tig;
            float v00 = acc[mt][nt][0] + b0, v01 = acc[mt][nt][1] + b0;
            float v10 = acc[mt][nt][2] + b1, v11 = acc[mt][nt][3] + b1;
            zb[(size_t)r0 * (NN / 2) + (cn >> 1)] = bf2(v00, v01);
            zb[(size_t)r1 * (NN / 2) + (cn >> 1)] = bf2(v10, v11);
            s0 += v00 + v01;  q0 += v00 * v00 + v01 * v01;
            s1 += v10 + v11;  q1 += v10 * v10 + v11 * v11;
        }
        s0 += __shfl_xor_sync(~0u, s0, 1); s0 += __shfl_xor_sync(~0u, s0, 2);
        q0 += __shfl_xor_sync(~0u, q0, 1); q0 += __shfl_xor_sync(~0u, q0, 2);
        s1 += __shfl_xor_sync(~0u, s1, 1); s1 += __shfl_xor_sync(~0u, s1, 2);
        q1 += __shfl_xor_sync(~0u, q1, 1); q1 += __shfl_xor_sync(~0u, q1, 2);
        if (tig == 0) {
            atomicAdd(&d_sums[m0 + r0], s0);       atomicAdd(&d_sums[256 + m0 + r0], q0);
            atomicAdd(&d_sums[m0 + r1], s1);       atomicAdd(&d_sums[256 + m0 + r1], q1);
        }
    }
}

// ---------------- Kernel 5: out = z*scale + shift + x (stats finalized inline) ----------------
__global__ __launch_bounds__(256) void bn_apply_kernel(
    const float* __restrict__ x, float* __restrict__ out,
    const float* __restrict__ gamma, const float* __restrict__ beta)
{
    const size_t i = (size_t)blockIdx.x * 256 + threadIdx.x;  // float4 index
    const int c = (int)((i >> 9) & (CC - 1));
    const float inv = 1.0f / (float)(BB * NN);
    float mean = d_sums[c] * inv;
    float var  = d_sums[256 + c] * inv - mean * mean;
    float sc   = gamma[c] * rsqrtf(var + 1e-5f);
    float sh   = beta[c] - mean * sc;
    uint2 zp = ((const uint2*)d_zb)[i];
    float4 xv = ((const float4*)x)[i];
    float z0 = __uint_as_float(zp.x << 16);
    float z1 = __uint_as_float(zp.x & 0xffff0000u);
    float z2 = __uint_as_float(zp.y << 16);
    float z3 = __uint_as_float(zp.y & 0xffff0000u);
    float4 o;
    o.x = z0 * sc + sh + xv.x;
    o.y = z1 * sc + sh + xv.y;
    o.z = z2 * sc + sh + xv.z;
    o.w = z3 * sc + sh + xv.w;
    ((float4*)out)[i] = o;
}

// ---------------- launch ----------------
extern "C" void kernel_launch(void* const* d_in, const int* in_sizes, int n_in,
                              void* d_out, int out_size)
{
    const float* x       = (const float*)d_in[0];
    const float* g_w     = (const float*)d_in[1];
    const float* g_b     = (const float*)d_in[2];
    const float* theta_w = (const float*)d_in[3];
    const float* theta_b = (const float*)d_in[4];
    const float* phi_w   = (const float*)d_in[5];
    const float* phi_b   = (const float*)d_in[6];
    const float* W_w     = (const float*)d_in[7];
    const float* W_b     = (const float*)d_in[8];
    const float* gamma   = (const float*)d_in[9];
    const float* beta    = (const float*)d_in[10];
    float* out = (float*)d_out;

    const int pf_smem = (128 + 128 + 64 + 64) * 136 * 4;   // 208896 bytes
    static bool attr_set = false;
    if (!attr_set) {
        cudaFuncSetAttribute(proj_fused_kernel, cudaFuncAttributeMaxDynamicSharedMemorySize, pf_smem);
        attr_set = true;
    }

    pack_kernel      <<<192, 256>>>(theta_w, theta_b, phi_w, phi_b, g_w, g_b, W_w);
    proj_fused_kernel<<<dim3(MSPLIT, BB), 256, pf_smem>>>(x);
    mred_kernel      <<<256, 256>>>();
    q_kernel         <<<dim3(2, BB), 256>>>();
    z_kernel         <<<dim3(NN / 128, 2, BB), 256>>>(W_b);
    bn_apply_kernel  <<<(size_t)(BB * CC * NN) / 4 / 256, 256>>>(x, out, gamma, beta);
}

// round 7
// speedup vs baseline: 4.5218x; 1.1179x over previous
#include <cuda_runtime.h>
#include <cstdint>

#define BB    16
#define CC    256
#define INTER 128
#define NN    2048
#define MSPLIT 8            // two 128-n slices per block

// ---------------- scratch ----------------
__device__ uint32_t d_Wtp [128 * 384];                 // bf16 pairs along k: [k2][m], m = theta|phi|g
__device__ float    d_Wt2 [128 * 256];                 // W_w^T fp32: [d][c]
__device__ float    d_bias[384];
__device__ uint32_t d_theta[(size_t)BB * INTER * (NN / 2)];   // bf16 pairs along n: [b][k][n2]
__device__ float    d_Mpart[(size_t)BB * MSPLIT * INTER * INTER];
__device__ float    d_Mred [(size_t)BB * INTER * INTER];
__device__ float    d_Qt   [(size_t)BB * INTER * CC];  // [b][k][c]
__device__ uint32_t d_zb   [(size_t)BB * CC * (NN / 2)];      // z as bf16 pairs along n
__device__ float    d_sums [512];

// ---------------- helpers ----------------
__device__ __forceinline__ uint32_t bf2(float lo, float hi) {
    uint32_t r; asm("cvt.rn.bf16x2.f32 %0,%1,%2;" : "=r"(r) : "f"(hi), "f"(lo));
    return r;
}
__device__ __forceinline__ void mma16(float* c, const uint32_t* a, const uint32_t* b) {
    asm volatile("mma.sync.aligned.m16n8k16.row.col.f32.bf16.bf16.f32 "
        "{%0,%1,%2,%3},{%4,%5,%6,%7},{%8,%9},{%0,%1,%2,%3};"
        : "+f"(c[0]), "+f"(c[1]), "+f"(c[2]), "+f"(c[3])
        : "r"(a[0]), "r"(a[1]), "r"(a[2]), "r"(a[3]), "r"(b[0]), "r"(b[1]));
}
__device__ __forceinline__ float tf32r(float f) {
    uint32_t r; asm("cvt.rna.tf32.f32 %0,%1;" : "=r"(r) : "f"(f));
    return __uint_as_float(r);
}
__device__ __forceinline__ void mma8(float* c, const uint32_t* a, const uint32_t* b) {
    asm volatile("mma.sync.aligned.m16n8k8.row.col.f32.tf32.tf32.f32 "
        "{%0,%1,%2,%3},{%4,%5,%6,%7},{%8,%9},{%0,%1,%2,%3};"
        : "+f"(c[0]), "+f"(c[1]), "+f"(c[2]), "+f"(c[3])
        : "r"(a[0]), "r"(a[1]), "r"(a[2]), "r"(a[3]), "r"(b[0]), "r"(b[1]));
}

// ---------------- bf16 mma over one 16-k slab (As/Bs are [8][136] slabs) ----------------
__device__ __forceinline__ void mma_tile16(
    const uint32_t (*As)[136], const uint32_t (*Bs)[136],
    float (&acc)[4][4][4], int wm, int wn, int gid, int tig)
{
    uint32_t a[4][4], b[4][2];
    #pragma unroll
    for (int mt = 0; mt < 4; mt++) {
        int row = wm + mt * 16 + gid;
        a[mt][0] = As[tig][row];
        a[mt][1] = As[tig][row + 8];
        a[mt][2] = As[tig + 4][row];
        a[mt][3] = As[tig + 4][row + 8];
    }
    #pragma unroll
    for (int nt = 0; nt < 4; nt++) {
        int cn = wn + nt * 8 + gid;
        b[nt][0] = Bs[tig][cn];
        b[nt][1] = Bs[tig + 4][cn];
    }
    #pragma unroll
    for (int mt = 0; mt < 4; mt++)
        #pragma unroll
        for (int nt = 0; nt < 4; nt++)
            mma16(acc[mt][nt], a[mt], b[nt]);
}

// fp32 row-major C store (optional bias)
__device__ __forceinline__ void store_tile(
    float* C, size_t ldc, const float* bias,
    float (&acc)[4][4][4], int wm, int wn, int gid, int tig)
{
    #pragma unroll
    for (int mt = 0; mt < 4; mt++) {
        int r0 = wm + mt * 16 + gid, r1 = r0 + 8;
        float b0 = bias ? bias[r0] : 0.0f;
        float b1 = bias ? bias[r1] : 0.0f;
        #pragma unroll
        for (int nt = 0; nt < 4; nt++) {
            int cn = wn + nt * 8 + 2 * tig;
            *(float2*)(C + (size_t)r0 * ldc + cn) =
                make_float2(acc[mt][nt][0] + b0, acc[mt][nt][1] + b0);
            *(float2*)(C + (size_t)r1 * ldc + cn) =
                make_float2(acc[mt][nt][2] + b1, acc[mt][nt][3] + b1);
        }
    }
}

#define WARP_IDX \
    const int tid = threadIdx.x; \
    const int wid = tid >> 5; \
    const int wm = (wid >> 2) * 64, wn = (wid & 3) * 32; \
    const int gid = (tid & 31) >> 2, tig = tid & 3;

// ---------------- Kernel 0: pack weights + zero sums ----------------
__global__ __launch_bounds__(256) void pack_kernel(
    const float* __restrict__ tw, const float* __restrict__ tb,
    const float* __restrict__ pw, const float* __restrict__ pb,
    const float* __restrict__ gw, const float* __restrict__ gb,
    const float* __restrict__ Ww)
{
    int i = blockIdx.x * 256 + threadIdx.x;   // 0 .. 49151
    {
        int k2 = i / 384, m = i - k2 * 384;
        const float* w = (m < 128) ? tw : (m < 256) ? pw : gw;
        float2 v = *(const float2*)(w + (size_t)(m & 127) * 256 + 2 * k2);
        d_Wtp[i] = bf2(v.x, v.y);
    }
    if (i < 128 * 256) {
        int d = i >> 8, c = i & 255;
        d_Wt2[i] = Ww[(size_t)c * 128 + d];
    }
    if (i < 384) d_bias[i] = (i < 128) ? tb[i] : (i < 256) ? pb[i - 128] : gb[i - 256];
    if (i < 512) d_sums[i] = 0.0f;
}

// ---------------- Kernel 1: fused theta/phi/g projections + M partial (2 n-slices/block) ----------------
__global__ __launch_bounds__(256, 1) void proj_fused_kernel(const float* __restrict__ x)
{
    extern __shared__ uint32_t sm32[];
    uint32_t (*xs)[136] = (uint32_t(*)[136])sm32;          // 128 rows
    uint32_t (*wp)[136] = xs + 128;                        // 128 rows
    uint32_t (*ps)[136] = wp + 128;                        // 64 rows
    uint32_t (*gs)[136] = ps + 64;                         // 64 rows
    WARP_IDX
    const int b = blockIdx.y, s = blockIdx.x;

    float accM[4][4][4] = {};

    #pragma unroll 1
    for (int half = 0; half < 2; half++) {
        const int n0 = (2 * s + half) * 128;
        const float* xg = x + (size_t)b * CC * NN + n0;

        // load x slab: xs[k2][n] = bf2(x[2k2][n], x[2k2+1][n])
        {
            int c = (tid & 31) * 4, kb = tid >> 5;
            #pragma unroll
            for (int it = 0; it < 16; it++) {
                int k2 = kb + it * 8;
                const float* p = xg + (size_t)(2 * k2) * NN + c;
                float4 u = *(const float4*)p;
                float4 v = *(const float4*)(p + NN);
                xs[k2][c + 0] = bf2(u.x, v.x);
                xs[k2][c + 1] = bf2(u.y, v.y);
                xs[k2][c + 2] = bf2(u.z, v.z);
                xs[k2][c + 3] = bf2(u.w, v.w);
            }
        }
        // theta weight panel
        {
            int m4 = (tid & 31) * 4, kb = tid >> 5;
            #pragma unroll
            for (int it = 0; it < 16; it++) {
                int k2 = kb + it * 8;
                *(uint4*)&wp[k2][m4] = *(const uint4*)(d_Wtp + (size_t)k2 * 384 + m4);
            }
        }
        __syncthreads();
        // theta GEMM
        {
            float acc[4][4][4] = {};
            #pragma unroll 4
            for (int st = 0; st < 16; st++)
                mma_tile16(wp + st * 8, xs + st * 8, acc, wm, wn, gid, tig);
            uint32_t* T = d_theta + (size_t)b * INTER * (NN / 2) + n0 / 2;
            #pragma unroll
            for (int mt = 0; mt < 4; mt++) {
                int r0 = wm + mt * 16 + gid, r1 = r0 + 8;
                float b0 = d_bias[r0], b1 = d_bias[r1];
                #pragma unroll
                for (int nt = 0; nt < 4; nt++) {
                    int cw = (wn + nt * 8 + 2 * tig) >> 1;
                    T[(size_t)r0 * (NN / 2) + cw] = bf2(acc[mt][nt][0] + b0, acc[mt][nt][1] + b0);
                    T[(size_t)r1 * (NN / 2) + cw] = bf2(acc[mt][nt][2] + b1, acc[mt][nt][3] + b1);
                }
            }
        }
        __syncthreads();
        // phi panel + GEMM -> ps
        {
            int m4 = (tid & 31) * 4, kb = tid >> 5;
            #pragma unroll
            for (int it = 0; it < 16; it++) {
                int k2 = kb + it * 8;
                *(uint4*)&wp[k2][m4] = *(const uint4*)(d_Wtp + (size_t)k2 * 384 + 128 + m4);
            }
        }
        __syncthreads();
        {
            float acc[4][4][4] = {};
            #pragma unroll 4
            for (int st = 0; st < 16; st++)
                mma_tile16(wp + st * 8, xs + st * 8, acc, wm, wn, gid, tig);
            #pragma unroll
            for (int mt = 0; mt < 4; mt++) {
                int r0 = wm + mt * 16 + gid, r1 = r0 + 8;
                float b0 = d_bias[128 + r0], b1 = d_bias[128 + r1];
                #pragma unroll
                for (int nt = 0; nt < 4; nt++) {
                    int n2 = (wn + nt * 8 + 2 * tig) >> 1;
                    ps[n2][r0] = bf2(acc[mt][nt][0] + b0, acc[mt][nt][1] + b0);
                    ps[n2][r1] = bf2(acc[mt][nt][2] + b1, acc[mt][nt][3] + b1);
                }
            }
        }
        __syncthreads();
        // g panel + GEMM -> gs
        {
            int m4 = (tid & 31) * 4, kb = tid >> 5;
            #pragma unroll
            for (int it = 0; it < 16; it++) {
                int k2 = kb + it * 8;
                *(uint4*)&wp[k2][m4] = *(const uint4*)(d_Wtp + (size_t)k2 * 384 + 256 + m4);
            }
        }
        __syncthreads();
        {
            float acc[4][4][4] = {};
            #pragma unroll 4
            for (int st = 0; st < 16; st++)
                mma_tile16(wp + st * 8, xs + st * 8, acc, wm, wn, gid, tig);
            #pragma unroll
            for (int mt = 0; mt < 4; mt++) {
                int r0 = wm + mt * 16 + gid, r1 = r0 + 8;
                float b0 = d_bias[256 + r0], b1 = d_bias[256 + r1];
                #pragma unroll
                for (int nt = 0; nt < 4; nt++) {
                    int n2 = (wn + nt * 8 + 2 * tig) >> 1;
                    gs[n2][r0] = bf2(acc[mt][nt][0] + b0, acc[mt][nt][1] + b0);
                    gs[n2][r1] = bf2(acc[mt][nt][2] + b1, acc[mt][nt][3] + b1);
                }
            }
        }
        __syncthreads();
        // M partial accumulate: Mpart[k][d] += sum_n phi[k,n] g[d,n]
        #pragma unroll 4
        for (int s2 = 0; s2 < 8; s2++)
            mma_tile16(ps + s2 * 8, gs + s2 * 8, accM, wm, wn, gid, tig);
        __syncthreads();   // before next half overwrites xs/ps/gs
    }
    store_tile(d_Mpart + (size_t)(b * MSPLIT + s) * INTER * INTER, INTER,
               nullptr, accM, wm, wn, gid, tig);
}

// ---------------- Kernel 2: reduce split partials, scale 1/N ----------------
__global__ __launch_bounds__(256) void mred_kernel()
{
    const int i = blockIdx.x * 256 + threadIdx.x;   // float4 index, 65536 total
    const int b = i >> 12, r = i & 4095;
    const float4* p = (const float4*)(d_Mpart + (size_t)b * MSPLIT * 16384) + r;
    float4 a = make_float4(0.f, 0.f, 0.f, 0.f);
    #pragma unroll
    for (int sp = 0; sp < MSPLIT; sp++) {
        float4 v = p[(size_t)sp * 4096];
        a.x += v.x; a.y += v.y; a.z += v.z; a.w += v.w;
    }
    const float inv = 1.0f / (float)NN;
    ((float4*)(d_Mred + (size_t)b * 16384))[r] =
        make_float4(a.x * inv, a.y * inv, a.z * inv, a.w * inv);
}

// ---------------- tf32 slab loaders ----------------
__device__ __forceinline__ void ld_nn(float (*S)[136], const float* src, size_t ld, int tid)
{
    int k = tid >> 4, c = (tid & 15) * 8;
    const float* p = src + (size_t)k * ld + c;
    float4 v0 = *(const float4*)p, v1 = *(const float4*)(p + 4);
    S[k][c + 0] = tf32r(v0.x); S[k][c + 1] = tf32r(v0.y);
    S[k][c + 2] = tf32r(v0.z); S[k][c + 3] = tf32r(v0.w);
    S[k][c + 4] = tf32r(v1.x); S[k][c + 5] = tf32r(v1.y);
    S[k][c + 6] = tf32r(v1.z); S[k][c + 7] = tf32r(v1.w);
}
__device__ __forceinline__ void ld_tt(float (*S)[136], const float* src, size_t ld, int tid)
{
    int r = tid >> 1, q = (tid & 1) * 8;
    const float* p = src + (size_t)r * ld + q;
    float4 v0 = *(const float4*)p, v1 = *(const float4*)(p + 4);
    S[q + 0][r] = tf32r(v0.x); S[q + 1][r] = tf32r(v0.y);
    S[q + 2][r] = tf32r(v0.z); S[q + 3][r] = tf32r(v0.w);
    S[q + 4][r] = tf32r(v1.x); S[q + 5][r] = tf32r(v1.y);
    S[q + 6][r] = tf32r(v1.z); S[q + 7][r] = tf32r(v1.w);
}
__device__ __forceinline__ void mma_tile8(
    const float (*As)[136], const float (*Bs)[136],
    float (&acc)[4][4][4], int wm, int wn, int gid, int tig)
{
    #pragma unroll
    for (int ks = 0; ks < 2; ks++) {
        uint32_t a[4][4], b[4][2];
        const int kc = ks * 8 + tig;
        #pragma unroll
        for (int mt = 0; mt < 4; mt++) {
            int row = wm + mt * 16 + gid;
            a[mt][0] = __float_as_uint(As[kc][row]);
            a[mt][1] = __float_as_uint(As[kc][row + 8]);
            a[mt][2] = __float_as_uint(As[kc + 4][row]);
            a[mt][3] = __float_as_uint(As[kc + 4][row + 8]);
        }
        #pragma unroll
        for (int nt = 0; nt < 4; nt++) {
            int cn = wn + nt * 8 + gid;
            b[nt][0] = __float_as_uint(Bs[kc][cn]);
            b[nt][1] = __float_as_uint(Bs[kc + 4][cn]);
        }
        #pragma unroll
        for (int mt = 0; mt < 4; mt++)
            #pragma unroll
            for (int nt = 0; nt < 4; nt++)
                mma8(acc[mt][nt], a[mt], b[nt]);
    }
}

// ---------------- Kernel 3 (tf32): Qt[k][c] = sum_d Mred[k][d] * Wt2[d][c] ----------------
// full K resident in smem: one sync, sync-free mainloop
__global__ __launch_bounds__(256, 1) void q_kernel()
{
    extern __shared__ float smf[];
    float (*As)[136] = (float(*)[136])smf;      // 128 rows: [d][k]
    float (*Bs)[136] = As + 128;                // 128 rows: [d][c]
    float acc[4][4][4] = {};
    WARP_IDX
    const int b = blockIdx.y, n0 = blockIdx.x * 128;
    const float* M = d_Mred + (size_t)b * INTER * INTER;
    #pragma unroll
    for (int st = 0; st < 8; st++) {
        ld_tt(As + st * 16, M + st * 16, INTER, tid);
        ld_nn(Bs + st * 16, d_Wt2 + (size_t)st * 16 * CC + n0, CC, tid);
    }
    __syncthreads();
    #pragma unroll 4
    for (int st = 0; st < 8; st++)
        mma_tile8(As + st * 16, Bs + st * 16, acc, wm, wn, gid, tig);
    store_tile(d_Qt + (size_t)b * INTER * CC + n0, CC, nullptr, acc, wm, wn, gid, tig);
}

// ---------------- bf16-pair loaders for z ----------------
__device__ __forceinline__ void ld_pair_f32(uint32_t (*S)[136], const float* src, size_t ld, int tid)
{
    int k2 = tid >> 5, c = (tid & 31) * 4;
    const float* p = src + (size_t)(2 * k2) * ld + c;
    float4 u = *(const float4*)p;
    float4 v = *(const float4*)(p + ld);
    S[k2][c + 0] = bf2(u.x, v.x);
    S[k2][c + 1] = bf2(u.y, v.y);
    S[k2][c + 2] = bf2(u.z, v.z);
    S[k2][c + 3] = bf2(u.w, v.w);
}
__device__ __forceinline__ void ld_pair_bf(uint32_t (*S)[136], const uint32_t* src, size_t ldw, int tid)
{
    int k2 = tid >> 5, c2 = (tid & 31) * 2;
    const uint32_t* p = src + (size_t)(2 * k2) * ldw + c2;
    uint32_t w00 = p[0], w01 = p[1];
    uint32_t w10 = p[ldw], w11 = p[ldw + 1];
    S[k2][c2 * 2 + 0] = __byte_perm(w00, w10, 0x5410);
    S[k2][c2 * 2 + 1] = __byte_perm(w00, w10, 0x7632);
    S[k2][c2 * 2 + 2] = __byte_perm(w01, w11, 0x5410);
    S[k2][c2 * 2 + 3] = __byte_perm(w01, w11, 0x7632);
}

// ---------------- Kernel 4: z = Q @ theta + W_b (bf16 out) + BN partial stats ----------------
// full K resident: one sync, sync-free mainloop
__global__ __launch_bounds__(256, 2) void z_kernel(const float* __restrict__ W_b)
{
    extern __shared__ uint32_t zsm[];
    uint32_t (*As)[136] = (uint32_t(*)[136])zsm;   // 64 rows: [k2][c]
    uint32_t (*Bs)[136] = As + 64;                 // 64 rows: [k2][n]
    float acc[4][4][4] = {};
    WARP_IDX
    const int b = blockIdx.z, m0 = blockIdx.y * 128, n0 = blockIdx.x * 128;
    const float* A = d_Qt + (size_t)b * INTER * CC + m0;            // [k][c]
    const uint32_t* B = d_theta + (size_t)b * INTER * (NN / 2) + n0 / 2;
    #pragma unroll
    for (int st = 0; st < 8; st++) {
        ld_pair_f32(As + st * 8, A + (size_t)st * 16 * CC, CC, tid);
        ld_pair_bf(Bs + st * 8, B + (size_t)st * 16 * (NN / 2), NN / 2, tid);
    }
    __syncthreads();
    #pragma unroll 4
    for (int st = 0; st < 8; st++)
        mma_tile16(As + st * 8, Bs + st * 8, acc, wm, wn, gid, tig);

    uint32_t* zb = d_zb + ((size_t)b * CC + m0) * (NN / 2) + n0 / 2;
    #pragma unroll
    for (int mt = 0; mt < 4; mt++) {
        int r0 = wm + mt * 16 + gid, r1 = r0 + 8;
        float b0 = W_b[m0 + r0], b1 = W_b[m0 + r1];
        float s0 = 0.f, q0 = 0.f, s1 = 0.f, q1 = 0.f;
        #pragma unroll
        for (int nt = 0; nt < 4; nt++) {
            int cn = wn + nt * 8 + 2 * tig;
            float v00 = acc[mt][nt][0] + b0, v01 = acc[mt][nt][1] + b0;
            float v10 = acc[mt][nt][2] + b1, v11 = acc[mt][nt][3] + b1;
            zb[(size_t)r0 * (NN / 2) + (cn >> 1)] = bf2(v00, v01);
            zb[(size_t)r1 * (NN / 2) + (cn >> 1)] = bf2(v10, v11);
            s0 += v00 + v01;  q0 += v00 * v00 + v01 * v01;
            s1 += v10 + v11;  q1 += v10 * v10 + v11 * v11;
        }
        s0 += __shfl_xor_sync(~0u, s0, 1); s0 += __shfl_xor_sync(~0u, s0, 2);
        q0 += __shfl_xor_sync(~0u, q0, 1); q0 += __shfl_xor_sync(~0u, q0, 2);
        s1 += __shfl_xor_sync(~0u, s1, 1); s1 += __shfl_xor_sync(~0u, s1, 2);
        q1 += __shfl_xor_sync(~0u, q1, 1); q1 += __shfl_xor_sync(~0u, q1, 2);
        if (tig == 0) {
            atomicAdd(&d_sums[m0 + r0], s0);       atomicAdd(&d_sums[256 + m0 + r0], q0);
            atomicAdd(&d_sums[m0 + r1], s1);       atomicAdd(&d_sums[256 + m0 + r1], q1);
        }
    }
}

// ---------------- Kernel 5: out = z*scale + shift + x (stats finalized inline) ----------------
__global__ __launch_bounds__(256) void bn_apply_kernel(
    const float* __restrict__ x, float* __restrict__ out,
    const float* __restrict__ gamma, const float* __restrict__ beta)
{
    const size_t i = (size_t)blockIdx.x * 256 + threadIdx.x;  // float4 index
    const int c = (int)((i >> 9) & (CC - 1));
    const float inv = 1.0f / (float)(BB * NN);
    float mean = d_sums[c] * inv;
    float var  = d_sums[256 + c] * inv - mean * mean;
    float sc   = gamma[c] * rsqrtf(var + 1e-5f);
    float sh   = beta[c] - mean * sc;
    uint2 zp = ((const uint2*)d_zb)[i];
    float4 xv = ((const float4*)x)[i];
    float z0 = __uint_as_float(zp.x << 16);
    float z1 = __uint_as_float(zp.x & 0xffff0000u);
    float z2 = __uint_as_float(zp.y << 16);
    float z3 = __uint_as_float(zp.y & 0xffff0000u);
    float4 o;
    o.x = z0 * sc + sh + xv.x;
    o.y = z1 * sc + sh + xv.y;
    o.z = z2 * sc + sh + xv.z;
    o.w = z3 * sc + sh + xv.w;
    ((float4*)out)[i] = o;
}

// ---------------- launch ----------------
extern "C" void kernel_launch(void* const* d_in, const int* in_sizes, int n_in,
                              void* d_out, int out_size)
{
    const float* x       = (const float*)d_in[0];
    const float* g_w     = (const float*)d_in[1];
    const float* g_b     = (const float*)d_in[2];
    const float* theta_w = (const float*)d_in[3];
    const float* theta_b = (const float*)d_in[4];
    const float* phi_w   = (const float*)d_in[5];
    const float* phi_b   = (const float*)d_in[6];
    const float* W_w     = (const float*)d_in[7];
    const float* W_b     = (const float*)d_in[8];
    const float* gamma   = (const float*)d_in[9];
    const float* beta    = (const float*)d_in[10];
    float* out = (float*)d_out;

    const int pf_smem = (128 + 128 + 64 + 64) * 136 * 4;   // 208896
    const int q_smem  = (128 + 128) * 136 * 4;             // 139264
    const int z_smem  = (64 + 64) * 136 * 4;               // 69632
    static bool attr_set = false;
    if (!attr_set) {
        cudaFuncSetAttribute(proj_fused_kernel, cudaFuncAttributeMaxDynamicSharedMemorySize, pf_smem);
        cudaFuncSetAttribute(q_kernel, cudaFuncAttributeMaxDynamicSharedMemorySize, q_smem);
        cudaFuncSetAttribute(z_kernel, cudaFuncAttributeMaxDynamicSharedMemorySize, z_smem);
        attr_set = true;
    }

    pack_kernel      <<<192, 256>>>(theta_w, theta_b, phi_w, phi_b, g_w, g_b, W_w);
    proj_fused_kernel<<<dim3(MSPLIT, BB), 256, pf_smem>>>(x);
    mred_kernel      <<<256, 256>>>();
    q_kernel         <<<dim3(2, BB), 256, q_smem>>>();
    z_kernel         <<<dim3(NN / 128, 2, BB), 256, z_smem>>>(W_b);
    bn_apply_kernel  <<<(size_t)(BB * CC * NN) / 4 / 256, 256>>>(x, out, gamma, beta);
}

// round 8
// speedup vs baseline: 4.6586x; 1.0303x over previous
#include <cuda_runtime.h>
#include <cstdint>

#define BB    16
#define CC    256
#define INTER 128
#define NN    2048
#define MSPLIT 8            // two 128-n slices per block

// ---------------- scratch ----------------
__device__ uint32_t d_Wtp [128 * 384];                 // bf16 pairs along k: [k2][m], m = theta|phi|g
__device__ uint32_t d_Wt2p[64 * 256];                  // W_w^T bf16 pairs along d: [d2][c]
__device__ float    d_bias[384];
__device__ uint32_t d_theta[(size_t)BB * INTER * (NN / 2)];   // bf16 pairs along n: [b][k][n2]
__device__ float    d_Mpart[(size_t)BB * MSPLIT * INTER * INTER];
__device__ float    d_Mred [(size_t)BB * INTER * INTER];
__device__ float    d_Qt   [(size_t)BB * INTER * CC];  // [b][k][c]
__device__ uint32_t d_zb   [(size_t)BB * CC * (NN / 2)];      // z as bf16 pairs along n
__device__ float    d_sums [512];

// ---------------- helpers ----------------
__device__ __forceinline__ uint32_t bf2(float lo, float hi) {
    uint32_t r; asm("cvt.rn.bf16x2.f32 %0,%1,%2;" : "=r"(r) : "f"(hi), "f"(lo));
    return r;
}
__device__ __forceinline__ void mma16(float* c, const uint32_t* a, const uint32_t* b) {
    asm volatile("mma.sync.aligned.m16n8k16.row.col.f32.bf16.bf16.f32 "
        "{%0,%1,%2,%3},{%4,%5,%6,%7},{%8,%9},{%0,%1,%2,%3};"
        : "+f"(c[0]), "+f"(c[1]), "+f"(c[2]), "+f"(c[3])
        : "r"(a[0]), "r"(a[1]), "r"(a[2]), "r"(a[3]), "r"(b[0]), "r"(b[1]));
}

// ---------------- bf16 mma over one 16-k slab (slabs are [8][136]) ----------------
__device__ __forceinline__ void mma_tile16(
    const uint32_t (*As)[136], const uint32_t (*Bs)[136],
    float (&acc)[4][4][4], int wm, int wn, int gid, int tig)
{
    uint32_t a[4][4], b[4][2];
    #pragma unroll
    for (int mt = 0; mt < 4; mt++) {
        int row = wm + mt * 16 + gid;
        a[mt][0] = As[tig][row];
        a[mt][1] = As[tig][row + 8];
        a[mt][2] = As[tig + 4][row];
        a[mt][3] = As[tig + 4][row + 8];
    }
    #pragma unroll
    for (int nt = 0; nt < 4; nt++) {
        int cn = wn + nt * 8 + gid;
        b[nt][0] = Bs[tig][cn];
        b[nt][1] = Bs[tig + 4][cn];
    }
    #pragma unroll
    for (int mt = 0; mt < 4; mt++)
        #pragma unroll
        for (int nt = 0; nt < 4; nt++)
            mma16(acc[mt][nt], a[mt], b[nt]);
}

// fp32 row-major C store (optional bias)
__device__ __forceinline__ void store_tile(
    float* C, size_t ldc, const float* bias,
    float (&acc)[4][4][4], int wm, int wn, int gid, int tig)
{
    #pragma unroll
    for (int mt = 0; mt < 4; mt++) {
        int r0 = wm + mt * 16 + gid, r1 = r0 + 8;
        float b0 = bias ? bias[r0] : 0.0f;
        float b1 = bias ? bias[r1] : 0.0f;
        #pragma unroll
        for (int nt = 0; nt < 4; nt++) {
            int cn = wn + nt * 8 + 2 * tig;
            *(float2*)(C + (size_t)r0 * ldc + cn) =
                make_float2(acc[mt][nt][0] + b0, acc[mt][nt][1] + b0);
            *(float2*)(C + (size_t)r1 * ldc + cn) =
                make_float2(acc[mt][nt][2] + b1, acc[mt][nt][3] + b1);
        }
    }
}

#define WARP_IDX \
    const int tid = threadIdx.x; \
    const int wid = tid >> 5; \
    const int wm = (wid >> 2) * 64, wn = (wid & 3) * 32; \
    const int gid = (tid & 31) >> 2, tig = tid & 3;

// ---------------- panel / x-slab loaders for proj ----------------
__device__ __forceinline__ void ld_panel_half(uint32_t (*wp)[136], const uint32_t* base, int koff, int tid)
{
    int m4 = (tid & 31) * 4, kb = tid >> 5;
    #pragma unroll
    for (int it = 0; it < 8; it++) {
        int k2 = koff + kb + it * 8;
        *(uint4*)&wp[k2][m4] = *(const uint4*)(base + (size_t)k2 * 384 + m4);
    }
}
__device__ __forceinline__ void pf_panel_half(uint4 (&r)[8], const uint32_t* base, int tid)
{
    int m4 = (tid & 31) * 4, kb = tid >> 5;
    #pragma unroll
    for (int it = 0; it < 8; it++)
        r[it] = *(const uint4*)(base + (size_t)(kb + it * 8) * 384 + m4);
}
__device__ __forceinline__ void st_panel_half(uint32_t (*wp)[136], uint4 (&r)[8], int tid)
{
    int m4 = (tid & 31) * 4, kb = tid >> 5;
    #pragma unroll
    for (int it = 0; it < 8; it++)
        *(uint4*)&wp[kb + it * 8][m4] = r[it];
}
__device__ __forceinline__ void load_xs(uint32_t (*xs)[136], const float* xg, int tid)
{
    int c = (tid & 31) * 4, kb = tid >> 5;
    #pragma unroll
    for (int it = 0; it < 16; it++) {
        int k2 = kb + it * 8;
        const float* p = xg + (size_t)(2 * k2) * NN + c;
        float4 u = *(const float4*)p;
        float4 v = *(const float4*)(p + NN);
        xs[k2][c + 0] = bf2(u.x, v.x);
        xs[k2][c + 1] = bf2(u.y, v.y);
        xs[k2][c + 2] = bf2(u.z, v.z);
        xs[k2][c + 3] = bf2(u.w, v.w);
    }
}

// ---------------- Kernel 0: pack weights + zero sums ----------------
__global__ __launch_bounds__(256) void pack_kernel(
    const float* __restrict__ tw, const float* __restrict__ tb,
    const float* __restrict__ pw, const float* __restrict__ pb,
    const float* __restrict__ gw, const float* __restrict__ gb,
    const float* __restrict__ Ww)
{
    int i = blockIdx.x * 256 + threadIdx.x;   // 0 .. 49151
    {
        int k2 = i / 384, m = i - k2 * 384;
        const float* w = (m < 128) ? tw : (m < 256) ? pw : gw;
        float2 v = *(const float2*)(w + (size_t)(m & 127) * 256 + 2 * k2);
        d_Wtp[i] = bf2(v.x, v.y);
    }
    if (i < 64 * 256) {
        int d2 = i >> 8, c = i & 255;
        const float* p = Ww + (size_t)c * 128 + 2 * d2;
        d_Wt2p[i] = bf2(p[0], p[1]);
    }
    if (i < 384) d_bias[i] = (i < 128) ? tb[i] : (i < 256) ? pb[i - 128] : gb[i - 256];
    if (i < 512) d_sums[i] = 0.0f;
}

// ---------------- Kernel 1: fused theta/phi/g projections + M partial ----------------
// 2 n-slices per block; weight panels register-prefetched under the mma stream.
__global__ __launch_bounds__(256, 1) void proj_fused_kernel(const float* __restrict__ x)
{
    extern __shared__ uint32_t sm32[];
    uint32_t (*xs)[136] = (uint32_t(*)[136])sm32;          // 128 rows
    uint32_t (*wp)[136] = xs + 128;                        // 128 rows
    uint32_t (*ps)[136] = wp + 128;                        // 64 rows
    uint32_t (*gs)[136] = ps + 64;                         // 64 rows
    WARP_IDX
    const int b = blockIdx.y, s = blockIdx.x;
    const float* xbase = x + (size_t)b * CC * NN;

    float accM[4][4][4] = {};
    uint4 pf[8];

    // initial: x slab for half 0 + full theta panel
    load_xs(xs, xbase + 2 * s * 128, tid);
    ld_panel_half(wp, d_Wtp, 0, tid);
    ld_panel_half(wp, d_Wtp, 64, tid);
    __syncthreads();

    #pragma unroll
    for (int half = 0; half < 2; half++) {
        const int n0 = (2 * s + half) * 128;

        // ---- theta GEMM (phi lower half prefetched under it) ----
        pf_panel_half(pf, d_Wtp + 128, tid);
        {
            float acc[4][4][4] = {};
            #pragma unroll
            for (int st = 0; st < 16; st++)
                mma_tile16(wp + st * 8, xs + st * 8, acc, wm, wn, gid, tig);
            uint32_t* T = d_theta + (size_t)b * INTER * (NN / 2) + n0 / 2;
            #pragma unroll
            for (int mt = 0; mt < 4; mt++) {
                int r0 = wm + mt * 16 + gid, r1 = r0 + 8;
                float b0 = d_bias[r0], b1 = d_bias[r1];
                #pragma unroll
                for (int nt = 0; nt < 4; nt++) {
                    int cw = (wn + nt * 8 + 2 * tig) >> 1;
                    T[(size_t)r0 * (NN / 2) + cw] = bf2(acc[mt][nt][0] + b0, acc[mt][nt][1] + b0);
                    T[(size_t)r1 * (NN / 2) + cw] = bf2(acc[mt][nt][2] + b1, acc[mt][nt][3] + b1);
                }
            }
        }
        __syncthreads();
        st_panel_half(wp, pf, tid);
        ld_panel_half(wp, d_Wtp + 128, 64, tid);
        __syncthreads();

        // ---- phi GEMM (g lower half prefetched under it) ----
        pf_panel_half(pf, d_Wtp + 256, tid);
        {
            float acc[4][4][4] = {};
            #pragma unroll
            for (int st = 0; st < 16; st++)
                mma_tile16(wp + st * 8, xs + st * 8, acc, wm, wn, gid, tig);
            #pragma unroll
            for (int mt = 0; mt < 4; mt++) {
                int r0 = wm + mt * 16 + gid, r1 = r0 + 8;
                float b0 = d_bias[128 + r0], b1 = d_bias[128 + r1];
                #pragma unroll
                for (int nt = 0; nt < 4; nt++) {
                    int n2 = (wn + nt * 8 + 2 * tig) >> 1;
                    ps[n2][r0] = bf2(acc[mt][nt][0] + b0, acc[mt][nt][1] + b0);
                    ps[n2][r1] = bf2(acc[mt][nt][2] + b1, acc[mt][nt][3] + b1);
                }
            }
        }
        __syncthreads();
        st_panel_half(wp, pf, tid);
        ld_panel_half(wp, d_Wtp + 256, 64, tid);
        __syncthreads();

        // ---- g GEMM (theta lower for next half prefetched under it) ----
        if (half == 0) pf_panel_half(pf, d_Wtp, tid);
        {
            float acc[4][4][4] = {};
            #pragma unroll
            for (int st = 0; st < 16; st++)
                mma_tile16(wp + st * 8, xs + st * 8, acc, wm, wn, gid, tig);
            #pragma unroll
            for (int mt = 0; mt < 4; mt++) {
                int r0 = wm + mt * 16 + gid, r1 = r0 + 8;
                float b0 = d_bias[256 + r0], b1 = d_bias[256 + r1];
                #pragma unroll
                for (int nt = 0; nt < 4; nt++) {
                    int n2 = (wn + nt * 8 + 2 * tig) >> 1;
                    gs[n2][r0] = bf2(acc[mt][nt][0] + b0, acc[mt][nt][1] + b0);
                    gs[n2][r1] = bf2(acc[mt][nt][2] + b1, acc[mt][nt][3] + b1);
                }
            }
        }
        __syncthreads();
        if (half == 0) {
            // next-half theta panel + x slab: issued here, latency hidden by GEMM_M
            st_panel_half(wp, pf, tid);
            ld_panel_half(wp, d_Wtp, 64, tid);
            load_xs(xs, xbase + (n0 + 128), tid);
        }
        // ---- M partial accumulate ----
        #pragma unroll
        for (int s2 = 0; s2 < 8; s2++)
            mma_tile16(ps + s2 * 8, gs + s2 * 8, accM, wm, wn, gid, tig);
        __syncthreads();
    }
    store_tile(d_Mpart + (size_t)(b * MSPLIT + s) * INTER * INTER, INTER,
               nullptr, accM, wm, wn, gid, tig);
}

// ---------------- Kernel 2: reduce split partials, scale 1/N ----------------
__global__ __launch_bounds__(256) void mred_kernel()
{
    const int i = blockIdx.x * 256 + threadIdx.x;   // float2 index, 131072 total
    const int b = i >> 13, r = i & 8191;
    const float2* p = (const float2*)(d_Mpart + (size_t)b * MSPLIT * 16384) + r;
    float2 a = make_float2(0.f, 0.f);
    #pragma unroll
    for (int sp = 0; sp < MSPLIT; sp++) {
        float2 v = p[(size_t)sp * 8192];
        a.x += v.x; a.y += v.y;
    }
    const float inv = 1.0f / (float)NN;
    ((float2*)(d_Mred + (size_t)b * 16384))[r] = make_float2(a.x * inv, a.y * inv);
}

// ---------------- Kernel 3: Qt[k][c] = sum_d Mred[k][d] * Wt2[d][c]  (bf16) ----------------
__global__ __launch_bounds__(256, 2) void q_kernel()
{
    extern __shared__ uint32_t qsm[];
    uint32_t (*As)[136] = (uint32_t(*)[136])qsm;   // 64 rows: [d2][k] pairs along d
    uint32_t (*Bs)[136] = As + 64;                 // 64 rows: [d2][c]
    float acc[4][4][4] = {};
    WARP_IDX
    const int b = blockIdx.y, n0 = blockIdx.x * 128;
    const float* M = d_Mred + (size_t)b * INTER * INTER;
    // A: transpose + cvt (pairs along d)
    {
        int r = tid >> 1, dq = (tid & 1) * 8;
        #pragma unroll
        for (int st = 0; st < 8; st++) {
            const float* p = M + (size_t)r * INTER + st * 16 + dq;
            float4 v0 = *(const float4*)p, v1 = *(const float4*)(p + 4);
            int q2 = st * 8 + (tid & 1) * 4;
            As[q2 + 0][r] = bf2(v0.x, v0.y);
            As[q2 + 1][r] = bf2(v0.z, v0.w);
            As[q2 + 2][r] = bf2(v1.x, v1.y);
            As[q2 + 3][r] = bf2(v1.z, v1.w);
        }
    }
    // B: straight copy slice of pre-packed W_w^T
    {
        int r = tid >> 2, c0 = (tid & 3) * 4;
        #pragma unroll
        for (int it = 0; it < 8; it++) {
            int c = c0 + it * 16;
            *(uint4*)&Bs[r][c] = *(const uint4*)(d_Wt2p + (size_t)r * 256 + n0 + c);
        }
    }
    __syncthreads();
    #pragma unroll
    for (int st = 0; st < 8; st++)
        mma_tile16(As + st * 8, Bs + st * 8, acc, wm, wn, gid, tig);
    store_tile(d_Qt + (size_t)b * INTER * CC + n0, CC, nullptr, acc, wm, wn, gid, tig);
}

// ---------------- bf16-pair loaders for z ----------------
__device__ __forceinline__ void ld_pair_f32(uint32_t (*S)[136], const float* src, size_t ld, int tid)
{
    int k2 = tid >> 5, c = (tid & 31) * 4;
    const float* p = src + (size_t)(2 * k2) * ld + c;
    float4 u = *(const float4*)p;
    float4 v = *(const float4*)(p + ld);
    S[k2][c + 0] = bf2(u.x, v.x);
    S[k2][c + 1] = bf2(u.y, v.y);
    S[k2][c + 2] = bf2(u.z, v.z);
    S[k2][c + 3] = bf2(u.w, v.w);
}
__device__ __forceinline__ void ld_pair_bf(uint32_t (*S)[136], const uint32_t* src, size_t ldw, int tid)
{
    int k2 = tid >> 5, c2 = (tid & 31) * 2;
    const uint32_t* p = src + (size_t)(2 * k2) * ldw + c2;
    uint32_t w00 = p[0], w01 = p[1];
    uint32_t w10 = p[ldw], w11 = p[ldw + 1];
    S[k2][c2 * 2 + 0] = __byte_perm(w00, w10, 0x5410);
    S[k2][c2 * 2 + 1] = __byte_perm(w00, w10, 0x7632);
    S[k2][c2 * 2 + 2] = __byte_perm(w01, w11, 0x5410);
    S[k2][c2 * 2 + 3] = __byte_perm(w01, w11, 0x7632);
}

// ---------------- Kernel 4: z = Q @ theta + W_b (bf16 out) + BN partial stats ----------------
__global__ __launch_bounds__(256, 2) void z_kernel(const float* __restrict__ W_b)
{
    extern __shared__ uint32_t zsm[];
    uint32_t (*As)[136] = (uint32_t(*)[136])zsm;   // 64 rows: [k2][c]
    uint32_t (*Bs)[136] = As + 64;                 // 64 rows: [k2][n]
    float acc[4][4][4] = {};
    WARP_IDX
    const int b = blockIdx.z, m0 = blockIdx.y * 128, n0 = blockIdx.x * 128;
    const float* A = d_Qt + (size_t)b * INTER * CC + m0;            // [k][c]
    const uint32_t* B = d_theta + (size_t)b * INTER * (NN / 2) + n0 / 2;
    #pragma unroll
    for (int st = 0; st < 8; st++) {
        ld_pair_f32(As + st * 8, A + (size_t)st * 16 * CC, CC, tid);
        ld_pair_bf(Bs + st * 8, B + (size_t)st * 16 * (NN / 2), NN / 2, tid);
    }
    __syncthreads();
    #pragma unroll
    for (int st = 0; st < 8; st++)
        mma_tile16(As + st * 8, Bs + st * 8, acc, wm, wn, gid, tig);

    uint32_t* zb = d_zb + ((size_t)b * CC + m0) * (NN / 2) + n0 / 2;
    #pragma unroll
    for (int mt = 0; mt < 4; mt++) {
        int r0 = wm + mt * 16 + gid, r1 = r0 + 8;
        float b0 = W_b[m0 + r0], b1 = W_b[m0 + r1];
        float s0 = 0.f, q0 = 0.f, s1 = 0.f, q1 = 0.f;
        #pragma unroll
        for (int nt = 0; nt < 4; nt++) {
            int cn = wn + nt * 8 + 2 * tig;
            float v00 = acc[mt][nt][0] + b0, v01 = acc[mt][nt][1] + b0;
            float v10 = acc[mt][nt][2] + b1, v11 = acc[mt][nt][3] + b1;
            zb[(size_t)r0 * (NN / 2) + (cn >> 1)] = bf2(v00, v01);
            zb[(size_t)r1 * (NN / 2) + (cn >> 1)] = bf2(v10, v11);
            s0 += v00 + v01;  q0 += v00 * v00 + v01 * v01;
            s1 += v10 + v11;  q1 += v10 * v10 + v11 * v11;
        }
        s0 += __shfl_xor_sync(~0u, s0, 1); s0 += __shfl_xor_sync(~0u, s0, 2);
        q0 += __shfl_xor_sync(~0u, q0, 1); q0 += __shfl_xor_sync(~0u, q0, 2);
        s1 += __shfl_xor_sync(~0u, s1, 1); s1 += __shfl_xor_sync(~0u, s1, 2);
        q1 += __shfl_xor_sync(~0u, q1, 1); q1 += __shfl_xor_sync(~0u, q1, 2);
        if (tig == 0) {
            atomicAdd(&d_sums[m0 + r0], s0);       atomicAdd(&d_sums[256 + m0 + r0], q0);
            atomicAdd(&d_sums[m0 + r1], s1);       atomicAdd(&d_sums[256 + m0 + r1], q1);
        }
    }
}

// ---------------- Kernel 5: out = z*scale + shift + x (stats finalized inline) ----------------
__global__ __launch_bounds__(256) void bn_apply_kernel(
    const float* __restrict__ x, float* __restrict__ out,
    const float* __restrict__ gamma, const float* __restrict__ beta)
{
    const size_t i = (size_t)blockIdx.x * 256 + threadIdx.x;  // float4 index
    const int c = (int)((i >> 9) & (CC - 1));
    const float inv = 1.0f / (float)(BB * NN);
    float mean = d_sums[c] * inv;
    float var  = d_sums[256 + c] * inv - mean * mean;
    float sc   = gamma[c] * rsqrtf(var + 1e-5f);
    float sh   = beta[c] - mean * sc;
    uint2 zp = ((const uint2*)d_zb)[i];
    float4 xv = ((const float4*)x)[i];
    float z0 = __uint_as_float(zp.x << 16);
    float z1 = __uint_as_float(zp.x & 0xffff0000u);
    float z2 = __uint_as_float(zp.y << 16);
    float z3 = __uint_as_float(zp.y & 0xffff0000u);
    float4 o;
    o.x = z0 * sc + sh + xv.x;
    o.y = z1 * sc + sh + xv.y;
    o.z = z2 * sc + sh + xv.z;
    o.w = z3 * sc + sh + xv.w;
    ((float4*)out)[i] = o;
}

// ---------------- launch ----------------
extern "C" void kernel_launch(void* const* d_in, const int* in_sizes, int n_in,
                              void* d_out, int out_size)
{
    const float* x       = (const float*)d_in[0];
    const float* g_w     = (const float*)d_in[1];
    const float* g_b     = (const float*)d_in[2];
    const float* theta_w = (const float*)d_in[3];
    const float* theta_b = (const float*)d_in[4];
    const float* phi_w   = (const float*)d_in[5];
    const float* phi_b   = (const float*)d_in[6];
    const float* W_w     = (const float*)d_in[7];
    const float* W_b     = (const float*)d_in[8];
    const float* gamma   = (const float*)d_in[9];
    const float* beta    = (const float*)d_in[10];
    float* out = (float*)d_out;

    const int pf_smem = (128 + 128 + 64 + 64) * 136 * 4;   // 208896
    const int q_smem  = (64 + 64) * 136 * 4;               // 69632
    const int z_smem  = (64 + 64) * 136 * 4;               // 69632
    static bool attr_set = false;
    if (!attr_set) {
        cudaFuncSetAttribute(proj_fused_kernel, cudaFuncAttributeMaxDynamicSharedMemorySize, pf_smem);
        cudaFuncSetAttribute(q_kernel, cudaFuncAttributeMaxDynamicSharedMemorySize, q_smem);
        cudaFuncSetAttribute(z_kernel, cudaFuncAttributeMaxDynamicSharedMemorySize, z_smem);
        attr_set = true;
    }

    pack_kernel      <<<192, 256>>>(theta_w, theta_b, phi_w, phi_b, g_w, g_b, W_w);
    proj_fused_kernel<<<dim3(MSPLIT, BB), 256, pf_smem>>>(x);
    mred_kernel      <<<512, 256>>>();
    q_kernel         <<<dim3(2, BB), 256, q_smem>>>();
    z_kernel         <<<dim3(NN / 128, 2, BB), 256, z_smem>>>(W_b);
    bn_apply_kernel  <<<(size_t)(BB * CC * NN) / 4 / 256, 256>>>(x, out, gamma, beta);
}